// round 1
// baseline (speedup 1.0000x reference)
#include <cuda_runtime.h>

#define DEV_INLINE __device__ __forceinline__

// ---------------- problem constants ----------------
constexpr int Bq = 32;        // batch
constexpr int Nq = 512;       // nodes
constexpr int Tq = 64;        // GRU timesteps
constexpr int Eq = 128;       // embedding dim
constexpr int Oq = 64;        // output dim
constexpr int NSTREAM = 4;    // (side0,cfg),(side0,lfg),(side1,cfg),(side1,lfg)
constexpr int BN = Bq * Nq;   // 16384 rows per stream
constexpr int NWORD = Nq / 32; // 16 mask words per row
constexpr int N_ITERS = 5;

// ---------------- device scratch (static, allocation-free) ----------------
__device__ __align__(128) float d_lit[2][BN * Eq];
__device__ __align__(128) float d_emb[NSTREAM][BN * Eq];
__device__ __align__(128) float d_new[NSTREAM][BN * Eq];
__device__ __align__(128) float d_tmp[NSTREAM][BN * Eq];
__device__ __align__(128) unsigned d_gb[NSTREAM][BN * NWORD];
__device__ __align__(128) float d_h1[NSTREAM][BN];
__device__ __align__(128) float d_h2[NSTREAM][BN];
__device__ __align__(128) float d_mx[NSTREAM][BN];
__device__ __align__(128) float d_iz[NSTREAM][BN];
__device__ __align__(128) float d_xz[2][Bq * Tq * 3 * Eq];
__device__ __align__(128) float d_sem[2][Bq * Eq];
__device__ __align__(128) float d_mid[2][Bq * 2 * Eq];

// ---------------- helpers ----------------
DEV_INLINE float lrelu(float x) { return x > 0.f ? x : 0.2f * x; }
DEV_INLINE float fsigmoid(float x) { return __fdividef(1.f, 1.f + __expf(-x)); }
DEV_INLINE float ftanh(float x) {
    float e = __expf(2.f * x);
    return 1.f - __fdividef(2.f, e + 1.f);
}

// ---------------- K1: pack 0/1 int graphs into bitmasks ----------------
__global__ void k_pack(const int* __restrict__ c1, const int* __restrict__ l1,
                       const int* __restrict__ c2, const int* __restrict__ l2) {
    int idx = blockIdx.x * blockDim.x + threadIdx.x;   // 4*BN*NWORD threads
    int w = idx & (NWORD - 1);
    int row = idx >> 4;            // [0, 4*BN)
    int s = row / BN;
    int bn = row - s * BN;
    const int* src = (s == 0) ? c1 : (s == 1) ? l1 : (s == 2) ? c2 : l2;
    src += (size_t)bn * Nq + w * 32;
    unsigned bits = 0u;
#pragma unroll
    for (int j = 0; j < 32; j++) bits |= (src[j] != 0) ? (1u << j) : 0u;
    d_gb[s][bn * NWORD + w] = bits;
}

// ---------------- K2: lit = LITERAL @ W_lit ; emb = relu(lit) ----------------
// block: 64 rows x 128 cols, 256 threads, dyn smem = W(64KB) + X(32KB)
__global__ void k_lit(const float* __restrict__ lit1, const float* __restrict__ lit2,
                      const float* __restrict__ w1, const float* __restrict__ w2) {
    extern __shared__ float sm[];
    float* Ws = sm;                 // [128*128]
    float* Xs = sm + Eq * Eq;       // [64*128]
    int side = blockIdx.x >> 8;
    int tile = blockIdx.x & 255;
    int tid = threadIdx.x;
    const float* W = side ? w2 : w1;
    const float* X = (side ? lit2 : lit1) + (size_t)tile * 64 * Eq;

    {
        float4* w4 = (float4*)Ws; const float4* g4 = (const float4*)W;
        for (int i = tid; i < Eq * Eq / 4; i += 256) w4[i] = g4[i];
        float4* x4 = (float4*)Xs; const float4* h4 = (const float4*)X;
        for (int i = tid; i < 64 * Eq / 4; i += 256) x4[i] = h4[i];
    }
    __syncthreads();

    int c = tid & 127, rh = tid >> 7;
    float acc[32];
#pragma unroll
    for (int r = 0; r < 32; r++) acc[r] = 0.f;
    for (int k = 0; k < Eq; k++) {
        float wv = Ws[k * Eq + c];
        const float* xp = Xs + (rh * 32) * Eq + k;
#pragma unroll
        for (int r = 0; r < 32; r++) acc[r] = fmaf(xp[r * Eq], wv, acc[r]);
    }
#pragma unroll
    for (int r = 0; r < 32; r++) {
        int row = tile * 64 + rh * 32 + r;
        float v = acc[r];
        d_lit[side][(size_t)row * Eq + c] = v;
        float rv = v > 0.f ? v : 0.f;
        d_emb[side * 2 + 0][(size_t)row * Eq + c] = rv;
        d_emb[side * 2 + 1][(size_t)row * Eq + c] = rv;
    }
}

// ---------------- K3: XZ = SEMANTIC @ gru_k + b_i  ([B*T,128]@[128,384]) ----------------
__global__ void k_xz(const float* __restrict__ sem1, const float* __restrict__ sem2,
                     const float* __restrict__ k1, const float* __restrict__ k2,
                     const float* __restrict__ gb1, const float* __restrict__ gb2) {
    extern __shared__ float sm[];
    float* Ws = sm;            // [128*128] per chunk
    float* Xs = sm + Eq * Eq;  // [64*128]
    int side = blockIdx.x >> 5;
    int tile = blockIdx.x & 31;
    int tid = threadIdx.x;
    const float* K = side ? k2 : k1;
    const float* BI = side ? gb2 : gb1;   // row 0 of [2,384]
    const float* X = (side ? sem2 : sem1) + (size_t)tile * 64 * Eq;
    {
        float4* x4 = (float4*)Xs; const float4* h4 = (const float4*)X;
        for (int i = tid; i < 64 * Eq / 4; i += 256) x4[i] = h4[i];
    }
    int c = tid & 127, rh = tid >> 7;
    for (int ch = 0; ch < 3; ch++) {
        __syncthreads();
        for (int i = tid; i < Eq * Eq; i += 256) {
            int kk = i >> 7; int cc = i & 127;
            Ws[i] = K[kk * 384 + ch * 128 + cc];
        }
        __syncthreads();
        float acc[32];
#pragma unroll
        for (int r = 0; r < 32; r++) acc[r] = 0.f;
        for (int k = 0; k < Eq; k++) {
            float wv = Ws[k * Eq + c];
            const float* xp = Xs + (rh * 32) * Eq + k;
#pragma unroll
            for (int r = 0; r < 32; r++) acc[r] = fmaf(xp[r * Eq], wv, acc[r]);
        }
        float bi = BI[ch * 128 + c];
#pragma unroll
        for (int r = 0; r < 32; r++) {
            int row = tile * 64 + rh * 32 + r;
            d_xz[side][(size_t)row * 384 + ch * 128 + c] = acc[r] + bi;
        }
    }
}

// ---------------- K4: GRU recurrence (one block per side,batch) ----------------
// 384 threads; rk (196KB) + h + hz + br in dynamic smem.
__global__ void k_gru(const float* __restrict__ rk1, const float* __restrict__ rk2,
                      const float* __restrict__ gb1, const float* __restrict__ gb2) {
    extern __shared__ float sm[];
    float* rks = sm;             // [128*384]
    float* hs = sm + 128 * 384;  // [128]
    float* hzs = hs + 128;       // [384]
    float* brs = hzs + 384;      // [384]
    int side = blockIdx.x >> 5;
    int b = blockIdx.x & 31;
    int tid = threadIdx.x;
    const float* rk = side ? rk2 : rk1;
    const float* GB = side ? gb2 : gb1;
    for (int i = tid; i < 128 * 384; i += 384) rks[i] = rk[i];
    brs[tid] = GB[384 + tid];
    if (tid < 128) hs[tid] = 0.f;
    __syncthreads();

    for (int t = 0; t < Tq; t++) {
        const float* xzr = d_xz[side] + ((size_t)(b * Tq + t)) * 384;
        float acc = brs[tid];
#pragma unroll 8
        for (int d = 0; d < 128; d++) acc = fmaf(hs[d], rks[d * 384 + tid], acc);
        hzs[tid] = acc;
        __syncthreads();
        if (tid < 128) {
            float z = fsigmoid(xzr[tid] + hzs[tid]);
            float r = fsigmoid(xzr[128 + tid] + hzs[128 + tid]);
            float hh = ftanh(xzr[256 + tid] + r * hzs[256 + tid]);
            hs[tid] = z * hs[tid] + (1.f - z) * hh;
        }
        __syncthreads();
    }
    if (tid < 128) d_sem[side][b * Eq + tid] = hs[tid];
}

// ---------------- K5: attention scores h1,h2 ----------------
__global__ void k_scores(const float* __restrict__ cw1, const float* __restrict__ cb1,
                         const float* __restrict__ cw2, const float* __restrict__ cb2,
                         const float* __restrict__ lw1, const float* __restrict__ lb1,
                         const float* __restrict__ lw2, const float* __restrict__ lb2) {
    __shared__ float w1s[Eq], w2s[Eq];
    int s = blockIdx.x >> 6;               // 64 blocks per stream
    int bn = (blockIdx.x & 63) * 256 + threadIdx.x;
    const float* w1 = (s & 1) ? lw1 : cw1;
    const float* w2 = (s & 1) ? lw2 : cw2;
    float b1 = ((s & 1) ? lb1 : cb1)[0];
    float b2 = ((s & 1) ? lb2 : cb2)[0];
    if (threadIdx.x < Eq) { w1s[threadIdx.x] = w1[threadIdx.x]; w2s[threadIdx.x] = w2[threadIdx.x]; }
    __syncthreads();
    const float4* er = (const float4*)(d_emb[s] + (size_t)bn * Eq);
    float s1 = 0.f, s2 = 0.f;
#pragma unroll
    for (int k = 0; k < 32; k++) {
        float4 v = er[k];
        s1 += v.x * w1s[4 * k] + v.y * w1s[4 * k + 1] + v.z * w1s[4 * k + 2] + v.w * w1s[4 * k + 3];
        s2 += v.x * w2s[4 * k] + v.y * w2s[4 * k + 1] + v.z * w2s[4 * k + 2] + v.w * w2s[4 * k + 3];
    }
    d_h1[s][bn] = s1 + b1;
    d_h2[s][bn] = s2 + b2;
}

// ---------------- K6: per-row softmax stats (max, 1/Z) over edges ----------------
__global__ void k_stats() {
    __shared__ float h2s[Nq];
    int s = blockIdx.x >> 5;
    int b = blockIdx.x & 31;
    int i = threadIdx.x;          // 512 threads = 512 rows
    h2s[i] = d_h2[s][b * Nq + i];
    __syncthreads();
    float h1i = d_h1[s][b * Nq + i];
    const unsigned* gr = &d_gb[s][(size_t)(b * Nq + i) * NWORD];
    float m = -1e30f;
#pragma unroll 4
    for (int w = 0; w < NWORD; w++) {
        unsigned bits = gr[w];
        for (int j2 = 0; j2 < 32; j2++)
            if ((bits >> j2) & 1u) m = fmaxf(m, lrelu(h1i + h2s[w * 32 + j2]));
    }
    float z = 0.f;
    if (m > -1e29f) {
#pragma unroll 4
        for (int w = 0; w < NWORD; w++) {
            unsigned bits = gr[w];
            for (int j2 = 0; j2 < 32; j2++)
                if ((bits >> j2) & 1u) z += __expf(lrelu(h1i + h2s[w * 32 + j2]) - m);
        }
        d_mx[s][b * Nq + i] = m;
        d_iz[s][b * Nq + i] = __fdividef(1.f, z);
    } else {
        d_mx[s][b * Nq + i] = 0.f;
        d_iz[s][b * Nq + i] = 0.f;
    }
}

// ---------------- K7: fused attention apply  newemb = (softmax*G) @ emb ----------------
// grid: NSTREAM * B * 8 i-tiles; 256 threads; A tile regenerated on the fly (never hits DRAM)
__global__ void k_av() {
    extern __shared__ float sm[];
    float* embJ = sm;                    // [64*128]
    float* aS = embJ + 64 * Eq;          // [64*64]
    float* h1s = aS + 64 * 64;           // [64]
    float* ms = h1s + 64;                // [64]
    float* izs = ms + 64;                // [64]
    float* h2s = izs + 64;               // [64]
    unsigned* gbs = (unsigned*)(h2s + 64);  // [128]

    int bx = blockIdx.x;
    int s = bx >> 8;                 // /(32*8)
    int rem = bx & 255;
    int b = rem >> 3;
    int it = rem & 7;
    int i0 = it * 64;
    int tid = threadIdx.x;

    if (tid < 64) {
        int row = b * Nq + i0 + tid;
        h1s[tid] = d_h1[s][row];
        ms[tid] = d_mx[s][row];
        izs[tid] = d_iz[s][row];
    }

    int c = tid & 127, rh = tid >> 7;
    float acc[32];
#pragma unroll
    for (int r = 0; r < 32; r++) acc[r] = 0.f;

    for (int jt = 0; jt < 8; jt++) {
        int j0 = jt * 64;
        __syncthreads();    // protect previous tile's reads
        {
            const float4* g4 = (const float4*)(d_emb[s] + (size_t)(b * Nq + j0) * Eq);
            float4* e4 = (float4*)embJ;
            for (int q = tid; q < 64 * Eq / 4; q += 256) e4[q] = g4[q];
        }
        if (tid < 64) h2s[tid] = d_h2[s][b * Nq + j0 + tid];
        if (tid < 128) {
            int row = tid >> 1, which = tid & 1;
            gbs[tid] = d_gb[s][(size_t)(b * Nq + i0 + row) * NWORD + jt * 2 + which];
        }
        __syncthreads();
        // build A tile
        for (int q = tid; q < 64 * 64; q += 256) {
            int i = q >> 6, j = q & 63;
            unsigned bits = gbs[i * 2 + (j >> 5)];
            float a = 0.f;
            if ((bits >> (j & 31)) & 1u) {
                float lr = lrelu(h1s[i] + h2s[j]);
                a = __expf(lr - ms[i]) * izs[i];
            }
            aS[q] = a;
        }
        __syncthreads();
        // MAC
        for (int j = 0; j < 64; j++) {
            float v = embJ[j * Eq + c];
            const float* ap = aS + (rh * 32) * 64 + j;
#pragma unroll
            for (int r = 0; r < 32; r++) acc[r] = fmaf(ap[r * 64], v, acc[r]);
        }
    }
#pragma unroll
    for (int r = 0; r < 32; r++)
        d_new[s][(size_t)(b * Nq + i0 + rh * 32 + r) * Eq + c] = acc[r];
}

// ---------------- K8: t = relu(newemb @ mlp1) ----------------
__global__ void k_mlpA(const float* __restrict__ W) {
    extern __shared__ float sm[];
    float* Ws = sm;
    float* Xs = sm + Eq * Eq;
    int tile = blockIdx.x;               // 1024 tiles covering 4*BN rows
    int tid = threadIdx.x;
    const float* X = &d_new[0][0] + (size_t)tile * 64 * Eq;
    {
        float4* w4 = (float4*)Ws; const float4* g4 = (const float4*)W;
        for (int i = tid; i < Eq * Eq / 4; i += 256) w4[i] = g4[i];
        float4* x4 = (float4*)Xs; const float4* h4 = (const float4*)X;
        for (int i = tid; i < 64 * Eq / 4; i += 256) x4[i] = h4[i];
    }
    __syncthreads();
    int c = tid & 127, rh = tid >> 7;
    float acc[32];
#pragma unroll
    for (int r = 0; r < 32; r++) acc[r] = 0.f;
    for (int k = 0; k < Eq; k++) {
        float wv = Ws[k * Eq + c];
        const float* xp = Xs + (rh * 32) * Eq + k;
#pragma unroll
        for (int r = 0; r < 32; r++) acc[r] = fmaf(xp[r * Eq], wv, acc[r]);
    }
#pragma unroll
    for (int r = 0; r < 32; r++) {
        size_t row = (size_t)tile * 64 + rh * 32 + r;
        float v = acc[r];
        (&d_tmp[0][0])[row * Eq + c] = v > 0.f ? v : 0.f;
    }
}

// ---------------- K9: emb = tanh(lit + t @ mlp2) ----------------
__global__ void k_mlpB(const float* __restrict__ W) {
    extern __shared__ float sm[];
    float* Ws = sm;
    float* Xs = sm + Eq * Eq;
    int tile = blockIdx.x;
    int tid = threadIdx.x;
    const float* X = &d_tmp[0][0] + (size_t)tile * 64 * Eq;
    {
        float4* w4 = (float4*)Ws; const float4* g4 = (const float4*)W;
        for (int i = tid; i < Eq * Eq / 4; i += 256) w4[i] = g4[i];
        float4* x4 = (float4*)Xs; const float4* h4 = (const float4*)X;
        for (int i = tid; i < 64 * Eq / 4; i += 256) x4[i] = h4[i];
    }
    __syncthreads();
    int c = tid & 127, rh = tid >> 7;
    float acc[32];
#pragma unroll
    for (int r = 0; r < 32; r++) acc[r] = 0.f;
    for (int k = 0; k < Eq; k++) {
        float wv = Ws[k * Eq + c];
        const float* xp = Xs + (rh * 32) * Eq + k;
#pragma unroll
        for (int r = 0; r < 32; r++) acc[r] = fmaf(xp[r * Eq], wv, acc[r]);
    }
    int s = (tile * 64) / BN;        // tile never straddles streams
    int side = s >> 1;
    int rbase = tile * 64 - s * BN;
#pragma unroll
    for (int r = 0; r < 32; r++) {
        int row = rbase + rh * 32 + r;
        float litv = d_lit[side][(size_t)row * Eq + c];
        (&d_emb[0][0])[((size_t)tile * 64 + rh * 32 + r) * Eq + c] = ftanh(litv + acc[r]);
    }
}

// ---------------- K10: mid = sum_N concat(cfg_e, lfg_e) ----------------
__global__ void k_colsum() {
    int side = blockIdx.x >> 5;
    int b = blockIdx.x & 31;
    int e2 = threadIdx.x;                 // 256
    int st = side * 2 + (e2 >> 7);
    int e = e2 & 127;
    float sum = 0.f;
    const float* base = d_emb[st] + (size_t)b * Nq * Eq + e;
    for (int i = 0; i < Nq; i++) sum += base[(size_t)i * Eq];
    d_mid[side][b * 256 + e2] = sum;
}

// ---------------- K11: output head + cosine ----------------
__global__ void k_final(const float* __restrict__ Wout, const float* __restrict__ bout,
                        float* __restrict__ out) {
    int b = blockIdx.x;
    int o = threadIdx.x;                  // 64 threads
    float e[2];
#pragma unroll
    for (int side = 0; side < 2; side++) {
        float a = bout[o];
        const float* mid = d_mid[side] + b * 256;
        for (int k = 0; k < 256; k++) a = fmaf(mid[k], Wout[k * Oq + o], a);
        const float* se = d_sem[side] + b * Eq;
        for (int k = 0; k < 128; k++) a = fmaf(se[k], Wout[(256 + k) * Oq + o], a);
        e[side] = a;
    }
    float p = e[0] * e[1], q0 = e[0] * e[0], q1 = e[1] * e[1];
#pragma unroll
    for (int off = 16; off; off >>= 1) {
        p += __shfl_xor_sync(0xffffffffu, p, off);
        q0 += __shfl_xor_sync(0xffffffffu, q0, off);
        q1 += __shfl_xor_sync(0xffffffffu, q1, off);
    }
    __shared__ float sp[2], s0[2], s1[2];
    if ((o & 31) == 0) { int w = o >> 5; sp[w] = p; s0[w] = q0; s1[w] = q1; }
    __syncthreads();
    if (o == 0) {
        float dot = sp[0] + sp[1];
        float n0 = s0[0] + s0[1];
        float n1 = s1[0] + s1[1];
        out[b] = 0.5f * (1.f + dot * rsqrtf(fmaxf(n0, 1e-12f)) * rsqrtf(fmaxf(n1, 1e-12f)));
    }
}

// ---------------- host launcher ----------------
constexpr int GEMM_SMEM = (Eq * Eq + 64 * Eq) * 4;               // 98304
constexpr int GRU_SMEM = (128 * 384 + 128 + 384 + 384) * 4;      // 200192
constexpr int AV_SMEM = (64 * Eq + 64 * 64 + 64 * 4) * 4 + 128 * 4;  // 50688

extern "C" void kernel_launch(void* const* d_in, const int* in_sizes, int n_in,
                              void* d_out, int out_size) {
    const int* CFG1 = (const int*)d_in[0];
    const int* LFG1 = (const int*)d_in[1];
    const float* LIT1 = (const float*)d_in[2];
    const float* SEM1 = (const float*)d_in[3];
    const int* CFG2 = (const int*)d_in[4];
    const int* LFG2 = (const int*)d_in[5];
    const float* LIT2 = (const float*)d_in[6];
    const float* SEM2 = (const float*)d_in[7];
    const float* Wlit1 = (const float*)d_in[8];
    const float* gk1 = (const float*)d_in[9];
    const float* grk1 = (const float*)d_in[10];
    const float* gb1 = (const float*)d_in[11];
    const float* Wlit2 = (const float*)d_in[12];
    const float* gk2 = (const float*)d_in[13];
    const float* grk2 = (const float*)d_in[14];
    const float* gb2 = (const float*)d_in[15];
    const float* ca1w = (const float*)d_in[16];
    const float* ca1b = (const float*)d_in[17];
    const float* ca2w = (const float*)d_in[18];
    const float* ca2b = (const float*)d_in[19];
    const float* la1w = (const float*)d_in[20];
    const float* la1b = (const float*)d_in[21];
    const float* la2w = (const float*)d_in[22];
    const float* la2b = (const float*)d_in[23];
    const float* mlp1 = (const float*)d_in[24];
    const float* mlp2 = (const float*)d_in[25];
    const float* Wout = (const float*)d_in[26];
    const float* bout = (const float*)d_in[27];
    float* out = (float*)d_out;

    cudaFuncSetAttribute(k_lit, cudaFuncAttributeMaxDynamicSharedMemorySize, GEMM_SMEM);
    cudaFuncSetAttribute(k_xz, cudaFuncAttributeMaxDynamicSharedMemorySize, GEMM_SMEM);
    cudaFuncSetAttribute(k_gru, cudaFuncAttributeMaxDynamicSharedMemorySize, GRU_SMEM);
    cudaFuncSetAttribute(k_av, cudaFuncAttributeMaxDynamicSharedMemorySize, AV_SMEM);
    cudaFuncSetAttribute(k_mlpA, cudaFuncAttributeMaxDynamicSharedMemorySize, GEMM_SMEM);
    cudaFuncSetAttribute(k_mlpB, cudaFuncAttributeMaxDynamicSharedMemorySize, GEMM_SMEM);

    k_pack<<<4 * BN * NWORD / 256, 256>>>(CFG1, LFG1, CFG2, LFG2);
    k_lit<<<512, 256, GEMM_SMEM>>>(LIT1, LIT2, Wlit1, Wlit2);
    k_xz<<<64, 256, GEMM_SMEM>>>(SEM1, SEM2, gk1, gk2, gb1, gb2);
    k_gru<<<64, 384, GRU_SMEM>>>(grk1, grk2, gb1, gb2);

    for (int it = 0; it < N_ITERS; it++) {
        k_scores<<<256, 256>>>(ca1w, ca1b, ca2w, ca2b, la1w, la1b, la2w, la2b);
        k_stats<<<128, 512>>>();
        k_av<<<NSTREAM * Bq * 8, 256, AV_SMEM>>>();
        k_mlpA<<<1024, 256, GEMM_SMEM>>>(mlp1);
        k_mlpB<<<1024, 256, GEMM_SMEM>>>(mlp2);
    }
    k_colsum<<<64, 256>>>();
    k_final<<<32, 64>>>(Wout, bout, out);
}

// round 2
// speedup vs baseline: 1.6887x; 1.6887x over previous
#include <cuda_runtime.h>

#define DEV_INLINE __device__ __forceinline__

// ---------------- problem constants ----------------
constexpr int Bq = 32;
constexpr int Nq = 512;
constexpr int Tq = 64;
constexpr int Eq = 128;
constexpr int Oq = 64;
constexpr int NSTREAM = 4;
constexpr int BN = Bq * Nq;
constexpr int NWORD = Nq / 32;
constexpr int N_ITERS = 5;

// ---------------- device scratch ----------------
__device__ __align__(128) float d_lit[2][BN * Eq];
__device__ __align__(128) float d_emb[NSTREAM][BN * Eq];
__device__ __align__(128) float d_new[NSTREAM][BN * Eq];
__device__ __align__(128) unsigned d_gb[NSTREAM][BN * NWORD];
__device__ __align__(128) float d_h1[NSTREAM][BN];
__device__ __align__(128) float d_h2[NSTREAM][BN];
__device__ __align__(128) float d_mx[NSTREAM][BN];
__device__ __align__(128) float d_iz[NSTREAM][BN];
__device__ __align__(128) float d_xz[2][Bq * Tq * 3 * Eq];
__device__ __align__(128) float d_sem[2][Bq * Eq];
__device__ __align__(128) float d_mid[2][Bq * 2 * Eq];

// ---------------- helpers ----------------
DEV_INLINE float lrelu(float x) { return x > 0.f ? x : 0.2f * x; }
DEV_INLINE float fsigmoid(float x) { return __fdividef(1.f, 1.f + __expf(-x)); }
DEV_INLINE float ftanh(float x) {
    float e = __expf(2.f * x);
    return 1.f - __fdividef(2.f, e + 1.f);
}

// ---------------- K1: pack 0/1 int graphs into bitmasks ----------------
__global__ void k_pack(const int* __restrict__ c1, const int* __restrict__ l1,
                       const int* __restrict__ c2, const int* __restrict__ l2) {
    int idx = blockIdx.x * blockDim.x + threadIdx.x;
    int w = idx & (NWORD - 1);
    int row = idx >> 4;
    int s = row / BN;
    int bn = row - s * BN;
    const int* src = (s == 0) ? c1 : (s == 1) ? l1 : (s == 2) ? c2 : l2;
    src += (size_t)bn * Nq + w * 32;
    unsigned bits = 0u;
#pragma unroll
    for (int j = 0; j < 32; j++) bits |= (src[j] != 0) ? (1u << j) : 0u;
    d_gb[s][bn * NWORD + w] = bits;
}

// ======== register-blocked MAC core: 256 thr, 64 rows x 128 cols, 8x4/thread ====
// Xs: [64][128] row-major, Ws: [128][128] row-major. acc[r][c].
#define MAC_64x128(Xs, Ws, acc, tx, ty)                                          \
    {                                                                            \
        _Pragma("unroll 4") for (int k = 0; k < Eq; k++) {                       \
            float4 wv = *(const float4*)&(Ws)[k * Eq + (tx) * 4];                \
            float xr[8];                                                         \
            _Pragma("unroll") for (int r = 0; r < 8; r++)                        \
                xr[r] = (Xs)[((ty) * 8 + r) * Eq + k];                           \
            _Pragma("unroll") for (int r = 0; r < 8; r++) {                      \
                acc[r][0] = fmaf(xr[r], wv.x, acc[r][0]);                        \
                acc[r][1] = fmaf(xr[r], wv.y, acc[r][1]);                        \
                acc[r][2] = fmaf(xr[r], wv.z, acc[r][2]);                        \
                acc[r][3] = fmaf(xr[r], wv.w, acc[r][3]);                        \
            }                                                                    \
        }                                                                        \
    }

// ---------------- K2: lit = LITERAL @ W_lit ; emb = relu(lit) ----------------
__global__ void k_lit(const float* __restrict__ lit1, const float* __restrict__ lit2,
                      const float* __restrict__ w1, const float* __restrict__ w2) {
    extern __shared__ float sm[];
    float* Ws = sm;                 // [128*128]
    float* Xs = sm + Eq * Eq;       // [64*128]
    int side = blockIdx.x >> 8;
    int tile = blockIdx.x & 255;
    int tid = threadIdx.x;
    const float* W = side ? w2 : w1;
    const float* X = (side ? lit2 : lit1) + (size_t)tile * 64 * Eq;
    {
        float4* w4 = (float4*)Ws; const float4* g4 = (const float4*)W;
        for (int i = tid; i < Eq * Eq / 4; i += 256) w4[i] = g4[i];
        float4* x4 = (float4*)Xs; const float4* h4 = (const float4*)X;
        for (int i = tid; i < 64 * Eq / 4; i += 256) x4[i] = h4[i];
    }
    __syncthreads();
    int tx = tid & 31, ty = tid >> 5;
    float acc[8][4];
#pragma unroll
    for (int r = 0; r < 8; r++)
#pragma unroll
        for (int c = 0; c < 4; c++) acc[r][c] = 0.f;
    MAC_64x128(Xs, Ws, acc, tx, ty);
#pragma unroll
    for (int r = 0; r < 8; r++) {
        int row = tile * 64 + ty * 8 + r;
        float4 v = make_float4(acc[r][0], acc[r][1], acc[r][2], acc[r][3]);
        *(float4*)&d_lit[side][(size_t)row * Eq + tx * 4] = v;
        float4 rv = make_float4(fmaxf(v.x, 0.f), fmaxf(v.y, 0.f), fmaxf(v.z, 0.f), fmaxf(v.w, 0.f));
        *(float4*)&d_emb[side * 2 + 0][(size_t)row * Eq + tx * 4] = rv;
        *(float4*)&d_emb[side * 2 + 1][(size_t)row * Eq + tx * 4] = rv;
    }
}

// ---------------- K3: XZ = SEMANTIC @ gru_k + b_i ----------------
__global__ void k_xz(const float* __restrict__ sem1, const float* __restrict__ sem2,
                     const float* __restrict__ k1, const float* __restrict__ k2,
                     const float* __restrict__ gb1, const float* __restrict__ gb2) {
    extern __shared__ float sm[];
    float* Ws = sm;
    float* Xs = sm + Eq * Eq;
    int side = blockIdx.x >> 5;
    int tile = blockIdx.x & 31;
    int tid = threadIdx.x;
    const float* K = side ? k2 : k1;
    const float* BI = side ? gb2 : gb1;
    const float* X = (side ? sem2 : sem1) + (size_t)tile * 64 * Eq;
    {
        float4* x4 = (float4*)Xs; const float4* h4 = (const float4*)X;
        for (int i = tid; i < 64 * Eq / 4; i += 256) x4[i] = h4[i];
    }
    int tx = tid & 31, ty = tid >> 5;
    for (int ch = 0; ch < 3; ch++) {
        __syncthreads();
        for (int i = tid; i < Eq * Eq; i += 256) {
            int kk = i >> 7; int cc = i & 127;
            Ws[i] = K[kk * 384 + ch * 128 + cc];
        }
        __syncthreads();
        float acc[8][4];
#pragma unroll
        for (int r = 0; r < 8; r++)
#pragma unroll
            for (int c = 0; c < 4; c++) acc[r][c] = 0.f;
        MAC_64x128(Xs, Ws, acc, tx, ty);
        float4 bi = *(const float4*)&BI[ch * 128 + tx * 4];
#pragma unroll
        for (int r = 0; r < 8; r++) {
            int row = tile * 64 + ty * 8 + r;
            float4 v = make_float4(acc[r][0] + bi.x, acc[r][1] + bi.y,
                                   acc[r][2] + bi.z, acc[r][3] + bi.w);
            *(float4*)&d_xz[side][(size_t)row * 384 + ch * 128 + tx * 4] = v;
        }
    }
}

// ---------------- K4: GRU recurrence ----------------
__global__ void k_gru(const float* __restrict__ rk1, const float* __restrict__ rk2,
                      const float* __restrict__ gb1, const float* __restrict__ gb2) {
    extern __shared__ float sm[];
    float* rks = sm;             // [128*384]
    float* hs = sm + 128 * 384;  // [128]
    float* hzs = hs + 128;       // [384]
    float* brs = hzs + 384;      // [384]
    int side = blockIdx.x >> 5;
    int b = blockIdx.x & 31;
    int tid = threadIdx.x;
    const float* rk = side ? rk2 : rk1;
    const float* GB = side ? gb2 : gb1;
    for (int i = tid; i < 128 * 384; i += 384) rks[i] = rk[i];
    brs[tid] = GB[384 + tid];
    if (tid < 128) hs[tid] = 0.f;
    __syncthreads();

    for (int t = 0; t < Tq; t++) {
        const float* xzr = d_xz[side] + ((size_t)(b * Tq + t)) * 384;
        float acc = brs[tid];
#pragma unroll 8
        for (int d4 = 0; d4 < 32; d4++) {
            float4 h4 = *(const float4*)&hs[d4 * 4];
            const float* rp = rks + (d4 * 4) * 384 + tid;
            acc = fmaf(h4.x, rp[0], acc);
            acc = fmaf(h4.y, rp[384], acc);
            acc = fmaf(h4.z, rp[768], acc);
            acc = fmaf(h4.w, rp[1152], acc);
        }
        hzs[tid] = acc;
        __syncthreads();
        if (tid < 128) {
            float z = fsigmoid(xzr[tid] + hzs[tid]);
            float r = fsigmoid(xzr[128 + tid] + hzs[128 + tid]);
            float hh = ftanh(xzr[256 + tid] + r * hzs[256 + tid]);
            hs[tid] = z * hs[tid] + (1.f - z) * hh;
        }
        __syncthreads();
    }
    if (tid < 128) d_sem[side][b * Eq + tid] = hs[tid];
}

// ---------------- K5: attention scores h1,h2 ----------------
__global__ void k_scores(const float* __restrict__ cw1, const float* __restrict__ cb1,
                         const float* __restrict__ cw2, const float* __restrict__ cb2,
                         const float* __restrict__ lw1, const float* __restrict__ lb1,
                         const float* __restrict__ lw2, const float* __restrict__ lb2) {
    __shared__ float w1s[Eq], w2s[Eq];
    int s = blockIdx.x >> 6;
    int bn = (blockIdx.x & 63) * 256 + threadIdx.x;
    const float* w1 = (s & 1) ? lw1 : cw1;
    const float* w2 = (s & 1) ? lw2 : cw2;
    float b1 = ((s & 1) ? lb1 : cb1)[0];
    float b2 = ((s & 1) ? lb2 : cb2)[0];
    if (threadIdx.x < Eq) { w1s[threadIdx.x] = w1[threadIdx.x]; w2s[threadIdx.x] = w2[threadIdx.x]; }
    __syncthreads();
    const float4* er = (const float4*)(d_emb[s] + (size_t)bn * Eq);
    float s1 = 0.f, s2 = 0.f;
#pragma unroll
    for (int k = 0; k < 32; k++) {
        float4 v = er[k];
        s1 += v.x * w1s[4 * k] + v.y * w1s[4 * k + 1] + v.z * w1s[4 * k + 2] + v.w * w1s[4 * k + 3];
        s2 += v.x * w2s[4 * k] + v.y * w2s[4 * k + 1] + v.z * w2s[4 * k + 2] + v.w * w2s[4 * k + 3];
    }
    d_h1[s][bn] = s1 + b1;
    d_h2[s][bn] = s2 + b2;
}

// ---------------- K6: per-row softmax stats ----------------
__global__ void k_stats() {
    __shared__ float h2s[Nq];
    int s = blockIdx.x >> 5;
    int b = blockIdx.x & 31;
    int i = threadIdx.x;
    h2s[i] = d_h2[s][b * Nq + i];
    __syncthreads();
    float h1i = d_h1[s][b * Nq + i];
    const unsigned* gr = &d_gb[s][(size_t)(b * Nq + i) * NWORD];
    float m = -1e30f;
#pragma unroll 4
    for (int w = 0; w < NWORD; w++) {
        unsigned bits = gr[w];
        for (int j2 = 0; j2 < 32; j2++)
            if ((bits >> j2) & 1u) m = fmaxf(m, lrelu(h1i + h2s[w * 32 + j2]));
    }
    float z = 0.f;
    if (m > -1e29f) {
#pragma unroll 4
        for (int w = 0; w < NWORD; w++) {
            unsigned bits = gr[w];
            for (int j2 = 0; j2 < 32; j2++)
                if ((bits >> j2) & 1u) z += __expf(lrelu(h1i + h2s[w * 32 + j2]) - m);
        }
        d_mx[s][b * Nq + i] = m;
        d_iz[s][b * Nq + i] = __fdividef(1.f, z);
    } else {
        d_mx[s][b * Nq + i] = 0.f;
        d_iz[s][b * Nq + i] = 0.f;
    }
}

// ---------------- K7: fused attention apply (register-blocked) ----------------
__global__ void k_av() {
    extern __shared__ float sm[];
    float* embJ = sm;                    // [64*128]
    float* aS = embJ + 64 * Eq;          // [64*64]  aS[i][j]
    float* h1s = aS + 64 * 64;
    float* ms = h1s + 64;
    float* izs = ms + 64;
    float* h2s = izs + 64;
    unsigned* gbs = (unsigned*)(h2s + 64);  // [128]

    int bx = blockIdx.x;
    int s = bx >> 8;
    int rem = bx & 255;
    int b = rem >> 3;
    int it = rem & 7;
    int i0 = it * 64;
    int tid = threadIdx.x;
    int tx = tid & 31, ty = tid >> 5;

    if (tid < 64) {
        int row = b * Nq + i0 + tid;
        h1s[tid] = d_h1[s][row];
        ms[tid] = d_mx[s][row];
        izs[tid] = d_iz[s][row];
    }

    float acc[8][4];
#pragma unroll
    for (int r = 0; r < 8; r++)
#pragma unroll
        for (int c = 0; c < 4; c++) acc[r][c] = 0.f;

    for (int jt = 0; jt < 8; jt++) {
        int j0 = jt * 64;
        __syncthreads();    // prev tile fully consumed
        {
            const float4* g4 = (const float4*)(d_emb[s] + (size_t)(b * Nq + j0) * Eq);
            float4* e4 = (float4*)embJ;
            for (int q = tid; q < 64 * Eq / 4; q += 256) e4[q] = g4[q];
        }
        if (tid < 64) h2s[tid] = d_h2[s][b * Nq + j0 + tid];
        if (tid < 128) {
            int row = tid >> 1, which = tid & 1;
            gbs[tid] = d_gb[s][(size_t)(b * Nq + i0 + row) * NWORD + jt * 2 + which];
        }
        __syncthreads();
        // build A tile (aS[i][j])
        for (int q = tid; q < 64 * 64; q += 256) {
            int i = q >> 6, j = q & 63;
            unsigned bits = gbs[i * 2 + (j >> 5)];
            float a = 0.f;
            if ((bits >> (j & 31)) & 1u) {
                float lr = lrelu(h1s[i] + h2s[j]);
                a = __expf(lr - ms[i]) * izs[i];
            }
            aS[q] = a;
        }
        __syncthreads();
        // MAC: rows = 8ty..8ty+7 of aS, cols = 4tx.. of embJ, K = 64
#pragma unroll 4
        for (int j = 0; j < 64; j++) {
            float4 ev = *(const float4*)&embJ[j * Eq + tx * 4];
            float ar[8];
#pragma unroll
            for (int r = 0; r < 8; r++) ar[r] = aS[(ty * 8 + r) * 64 + j];
#pragma unroll
            for (int r = 0; r < 8; r++) {
                acc[r][0] = fmaf(ar[r], ev.x, acc[r][0]);
                acc[r][1] = fmaf(ar[r], ev.y, acc[r][1]);
                acc[r][2] = fmaf(ar[r], ev.z, acc[r][2]);
                acc[r][3] = fmaf(ar[r], ev.w, acc[r][3]);
            }
        }
    }
#pragma unroll
    for (int r = 0; r < 8; r++) {
        float4 v = make_float4(acc[r][0], acc[r][1], acc[r][2], acc[r][3]);
        *(float4*)&d_new[s][(size_t)(b * Nq + i0 + ty * 8 + r) * Eq + tx * 4] = v;
    }
}

// ---------------- K8: fused MLP  emb = tanh(lit + relu(new@W1)@W2) ----------------
__global__ void k_mlp(const float* __restrict__ W1, const float* __restrict__ W2) {
    extern __shared__ float sm[];
    float* Xs = sm;                 // [64*128]
    float* Ws = sm + 64 * Eq;       // [128*128]
    float* Ts = Ws + Eq * Eq;       // [64*128]
    int tile = blockIdx.x;          // 1024 tiles over 4*BN rows
    int tid = threadIdx.x;
    int tx = tid & 31, ty = tid >> 5;
    const float* X = &d_new[0][0] + (size_t)tile * 64 * Eq;
    {
        float4* x4 = (float4*)Xs; const float4* h4 = (const float4*)X;
        for (int i = tid; i < 64 * Eq / 4; i += 256) x4[i] = h4[i];
        float4* w4 = (float4*)Ws; const float4* g4 = (const float4*)W1;
        for (int i = tid; i < Eq * Eq / 4; i += 256) w4[i] = g4[i];
    }
    __syncthreads();
    float acc[8][4];
#pragma unroll
    for (int r = 0; r < 8; r++)
#pragma unroll
        for (int c = 0; c < 4; c++) acc[r][c] = 0.f;
    MAC_64x128(Xs, Ws, acc, tx, ty);
    __syncthreads();   // all reads of Ws(W1) done
    {
        // store relu(T) and load W2
#pragma unroll
        for (int r = 0; r < 8; r++) {
            float4 v = make_float4(fmaxf(acc[r][0], 0.f), fmaxf(acc[r][1], 0.f),
                                   fmaxf(acc[r][2], 0.f), fmaxf(acc[r][3], 0.f));
            *(float4*)&Ts[(ty * 8 + r) * Eq + tx * 4] = v;
        }
        float4* w4 = (float4*)Ws; const float4* g4 = (const float4*)W2;
        for (int i = tid; i < Eq * Eq / 4; i += 256) w4[i] = g4[i];
    }
    __syncthreads();
#pragma unroll
    for (int r = 0; r < 8; r++)
#pragma unroll
        for (int c = 0; c < 4; c++) acc[r][c] = 0.f;
    MAC_64x128(Ts, Ws, acc, tx, ty);

    int s = (tile * 64) / BN;
    int side = s >> 1;
    int rbase = tile * 64 - s * BN;
#pragma unroll
    for (int r = 0; r < 8; r++) {
        int row = rbase + ty * 8 + r;
        float4 lv = *(const float4*)&d_lit[side][(size_t)row * Eq + tx * 4];
        float4 v = make_float4(ftanh(lv.x + acc[r][0]), ftanh(lv.y + acc[r][1]),
                               ftanh(lv.z + acc[r][2]), ftanh(lv.w + acc[r][3]));
        *(float4*)&(&d_emb[0][0])[((size_t)tile * 64 + ty * 8 + r) * Eq + tx * 4] = v;
    }
}

// ---------------- K10: mid = sum_N concat(cfg_e, lfg_e) ----------------
__global__ void k_colsum() {
    int side = blockIdx.x >> 5;
    int b = blockIdx.x & 31;
    int e2 = threadIdx.x;
    int st = side * 2 + (e2 >> 7);
    int e = e2 & 127;
    float sum = 0.f;
    const float* base = d_emb[st] + (size_t)b * Nq * Eq + e;
    for (int i = 0; i < Nq; i++) sum += base[(size_t)i * Eq];
    d_mid[side][b * 256 + e2] = sum;
}

// ---------------- K11: output head + cosine ----------------
__global__ void k_final(const float* __restrict__ Wout, const float* __restrict__ bout,
                        float* __restrict__ out) {
    int b = blockIdx.x;
    int o = threadIdx.x;
    float e[2];
#pragma unroll
    for (int side = 0; side < 2; side++) {
        float a = bout[o];
        const float* mid = d_mid[side] + b * 256;
        for (int k = 0; k < 256; k++) a = fmaf(mid[k], Wout[k * Oq + o], a);
        const float* se = d_sem[side] + b * Eq;
        for (int k = 0; k < 128; k++) a = fmaf(se[k], Wout[(256 + k) * Oq + o], a);
        e[side] = a;
    }
    float p = e[0] * e[1], q0 = e[0] * e[0], q1 = e[1] * e[1];
#pragma unroll
    for (int off = 16; off; off >>= 1) {
        p += __shfl_xor_sync(0xffffffffu, p, off);
        q0 += __shfl_xor_sync(0xffffffffu, q0, off);
        q1 += __shfl_xor_sync(0xffffffffu, q1, off);
    }
    __shared__ float sp[2], s0[2], s1[2];
    if ((o & 31) == 0) { int w = o >> 5; sp[w] = p; s0[w] = q0; s1[w] = q1; }
    __syncthreads();
    if (o == 0) {
        float dot = sp[0] + sp[1];
        float n0 = s0[0] + s0[1];
        float n1 = s1[0] + s1[1];
        out[b] = 0.5f * (1.f + dot * rsqrtf(fmaxf(n0, 1e-12f)) * rsqrtf(fmaxf(n1, 1e-12f)));
    }
}

// ---------------- host launcher ----------------
constexpr int GEMM_SMEM = (Eq * Eq + 64 * Eq) * 4;                    // 98304
constexpr int MLP_SMEM = (Eq * Eq + 2 * 64 * Eq) * 4;                 // 131072
constexpr int GRU_SMEM = (128 * 384 + 128 + 384 + 384) * 4;           // 200192
constexpr int AV_SMEM = (64 * Eq + 64 * 64 + 64 * 4) * 4 + 128 * 4;   // 50688

extern "C" void kernel_launch(void* const* d_in, const int* in_sizes, int n_in,
                              void* d_out, int out_size) {
    const int* CFG1 = (const int*)d_in[0];
    const int* LFG1 = (const int*)d_in[1];
    const float* LIT1 = (const float*)d_in[2];
    const float* SEM1 = (const float*)d_in[3];
    const int* CFG2 = (const int*)d_in[4];
    const int* LFG2 = (const int*)d_in[5];
    const float* LIT2 = (const float*)d_in[6];
    const float* SEM2 = (const float*)d_in[7];
    const float* Wlit1 = (const float*)d_in[8];
    const float* gk1 = (const float*)d_in[9];
    const float* grk1 = (const float*)d_in[10];
    const float* gb1 = (const float*)d_in[11];
    const float* Wlit2 = (const float*)d_in[12];
    const float* gk2 = (const float*)d_in[13];
    const float* grk2 = (const float*)d_in[14];
    const float* gb2 = (const float*)d_in[15];
    const float* ca1w = (const float*)d_in[16];
    const float* ca1b = (const float*)d_in[17];
    const float* ca2w = (const float*)d_in[18];
    const float* ca2b = (const float*)d_in[19];
    const float* la1w = (const float*)d_in[20];
    const float* la1b = (const float*)d_in[21];
    const float* la2w = (const float*)d_in[22];
    const float* la2b = (const float*)d_in[23];
    const float* mlp1 = (const float*)d_in[24];
    const float* mlp2 = (const float*)d_in[25];
    const float* Wout = (const float*)d_in[26];
    const float* bout = (const float*)d_in[27];
    float* out = (float*)d_out;

    cudaFuncSetAttribute(k_lit, cudaFuncAttributeMaxDynamicSharedMemorySize, GEMM_SMEM);
    cudaFuncSetAttribute(k_xz, cudaFuncAttributeMaxDynamicSharedMemorySize, GEMM_SMEM);
    cudaFuncSetAttribute(k_gru, cudaFuncAttributeMaxDynamicSharedMemorySize, GRU_SMEM);
    cudaFuncSetAttribute(k_av, cudaFuncAttributeMaxDynamicSharedMemorySize, AV_SMEM);
    cudaFuncSetAttribute(k_mlp, cudaFuncAttributeMaxDynamicSharedMemorySize, MLP_SMEM);

    k_pack<<<4 * BN * NWORD / 256, 256>>>(CFG1, LFG1, CFG2, LFG2);
    k_lit<<<512, 256, GEMM_SMEM>>>(LIT1, LIT2, Wlit1, Wlit2);
    k_xz<<<64, 256, GEMM_SMEM>>>(SEM1, SEM2, gk1, gk2, gb1, gb2);
    k_gru<<<64, 384, GRU_SMEM>>>(grk1, grk2, gb1, gb2);

    for (int it = 0; it < N_ITERS; it++) {
        k_scores<<<256, 256>>>(ca1w, ca1b, ca2w, ca2b, la1w, la1b, la2w, la2b);
        k_stats<<<128, 512>>>();
        k_av<<<NSTREAM * Bq * 8, 256, AV_SMEM>>>();
        k_mlp<<<1024, 256, MLP_SMEM>>>(mlp1, mlp2);
    }
    k_colsum<<<64, 256>>>();
    k_final<<<32, 64>>>(Wout, bout, out);
}

// round 3
// speedup vs baseline: 2.9709x; 1.7593x over previous
#include <cuda_runtime.h>

#define DEV_INLINE __device__ __forceinline__

// ---------------- problem constants ----------------
constexpr int Bq = 32;
constexpr int Nq = 512;
constexpr int Tq = 64;
constexpr int Eq = 128;
constexpr int Oq = 64;
constexpr int NSTREAM = 4;
constexpr int BN = Bq * Nq;
constexpr int NWORD = Nq / 32;
constexpr int N_ITERS = 5;

// ---------------- device scratch ----------------
__device__ __align__(128) float d_lit[2][BN * Eq];
__device__ __align__(128) float d_emb[NSTREAM][BN * Eq];   // fp32 (scores/colsum)
__device__ __align__(128) float d_embt[NSTREAM][BN * Eq];  // tf32-rounded (mma B operand)
__device__ __align__(128) float d_new[NSTREAM][BN * Eq];
__device__ __align__(128) unsigned d_gb[NSTREAM][BN * NWORD];
__device__ __align__(128) float d_h1[NSTREAM][BN];
__device__ __align__(128) float d_h2[NSTREAM][BN];
__device__ __align__(128) float d_mx[NSTREAM][BN];
__device__ __align__(128) float d_iz[NSTREAM][BN];
__device__ __align__(128) float d_xz[2][Bq * Tq * 3 * Eq];
__device__ __align__(128) float d_sem[2][Bq * Eq];
__device__ __align__(128) float d_mid[2][Bq * 2 * Eq];

// ---------------- helpers ----------------
DEV_INLINE float lrelu(float x) { return x > 0.f ? x : 0.2f * x; }
DEV_INLINE float fsigmoid(float x) { return __fdividef(1.f, 1.f + __expf(-x)); }
DEV_INLINE float ftanh(float x) {
    float e = __expf(2.f * x);
    return 1.f - __fdividef(2.f, e + 1.f);
}
DEV_INLINE unsigned cvt_tf32(float x) {
    unsigned r;
    asm("cvt.rna.tf32.f32 %0, %1;" : "=r"(r) : "f"(x));
    return r;
}
DEV_INLINE float tf32f(float x) { return __uint_as_float(cvt_tf32(x)); }

// ======== tf32 mma core: 64 rows x 128 cols tile, 8 warps ========
// warp w: wm = w>>1 (row base 16*wm), wn = w&1 (col base 64*wn)
// A operand Xs stride SX ≡ 4 (mod 32); B operand Ws stride SW ≡ 8 (mod 32)
template <int KSTEPS, int SX, int SW>
DEV_INLINE void mma_mac(const float* Xs, const float* Ws, float acc[8][4],
                        int mr, int cn, int g, int tg) {
#pragma unroll
    for (int ks = 0; ks < KSTEPS; ks++) {
        int k0 = ks * 8;
        unsigned a0 = __float_as_uint(Xs[(mr + g) * SX + k0 + tg]);
        unsigned a1 = __float_as_uint(Xs[(mr + g + 8) * SX + k0 + tg]);
        unsigned a2 = __float_as_uint(Xs[(mr + g) * SX + k0 + tg + 4]);
        unsigned a3 = __float_as_uint(Xs[(mr + g + 8) * SX + k0 + tg + 4]);
#pragma unroll
        for (int nt = 0; nt < 8; nt++) {
            int n = cn + nt * 8;
            unsigned b0 = __float_as_uint(Ws[(k0 + tg) * SW + n + g]);
            unsigned b1 = __float_as_uint(Ws[(k0 + tg + 4) * SW + n + g]);
            asm("mma.sync.aligned.m16n8k8.row.col.f32.tf32.tf32.f32 "
                "{%0,%1,%2,%3}, {%4,%5,%6,%7}, {%8,%9}, {%0,%1,%2,%3};"
                : "+f"(acc[nt][0]), "+f"(acc[nt][1]), "+f"(acc[nt][2]), "+f"(acc[nt][3])
                : "r"(a0), "r"(a1), "r"(a2), "r"(a3), "r"(b0), "r"(b1));
        }
    }
}

// ---------------- K1: pack 0/1 int graphs into bitmasks ----------------
__global__ void k_pack(const int* __restrict__ c1, const int* __restrict__ l1,
                       const int* __restrict__ c2, const int* __restrict__ l2) {
    int idx = blockIdx.x * blockDim.x + threadIdx.x;
    int w = idx & (NWORD - 1);
    int row = idx >> 4;
    int s = row / BN;
    int bn = row - s * BN;
    const int* src = (s == 0) ? c1 : (s == 1) ? l1 : (s == 2) ? c2 : l2;
    src += (size_t)bn * Nq + w * 32;
    unsigned bits = 0u;
#pragma unroll
    for (int j = 0; j < 32; j++) bits |= (src[j] != 0) ? (1u << j) : 0u;
    d_gb[s][bn * NWORD + w] = bits;
}

// ======== scalar register-blocked MAC (setup GEMMs) ========
#define MAC_64x128(Xs, Ws, acc, tx, ty)                                          \
    {                                                                            \
        _Pragma("unroll 4") for (int k = 0; k < Eq; k++) {                       \
            float4 wv = *(const float4*)&(Ws)[k * Eq + (tx) * 4];                \
            float xr[8];                                                         \
            _Pragma("unroll") for (int r = 0; r < 8; r++)                        \
                xr[r] = (Xs)[((ty) * 8 + r) * Eq + k];                           \
            _Pragma("unroll") for (int r = 0; r < 8; r++) {                      \
                acc[r][0] = fmaf(xr[r], wv.x, acc[r][0]);                        \
                acc[r][1] = fmaf(xr[r], wv.y, acc[r][1]);                        \
                acc[r][2] = fmaf(xr[r], wv.z, acc[r][2]);                        \
                acc[r][3] = fmaf(xr[r], wv.w, acc[r][3]);                        \
            }                                                                    \
        }                                                                        \
    }

// ---------------- K2: lit = LITERAL @ W_lit ; emb = relu(lit) ----------------
__global__ void k_lit(const float* __restrict__ lit1, const float* __restrict__ lit2,
                      const float* __restrict__ w1, const float* __restrict__ w2) {
    extern __shared__ float sm[];
    float* Ws = sm;
    float* Xs = sm + Eq * Eq;
    int side = blockIdx.x >> 8;
    int tile = blockIdx.x & 255;
    int tid = threadIdx.x;
    const float* W = side ? w2 : w1;
    const float* X = (side ? lit2 : lit1) + (size_t)tile * 64 * Eq;
    {
        float4* w4 = (float4*)Ws; const float4* g4 = (const float4*)W;
        for (int i = tid; i < Eq * Eq / 4; i += 256) w4[i] = g4[i];
        float4* x4 = (float4*)Xs; const float4* h4 = (const float4*)X;
        for (int i = tid; i < 64 * Eq / 4; i += 256) x4[i] = h4[i];
    }
    __syncthreads();
    int tx = tid & 31, ty = tid >> 5;
    float acc[8][4];
#pragma unroll
    for (int r = 0; r < 8; r++)
#pragma unroll
        for (int c = 0; c < 4; c++) acc[r][c] = 0.f;
    MAC_64x128(Xs, Ws, acc, tx, ty);
#pragma unroll
    for (int r = 0; r < 8; r++) {
        int row = tile * 64 + ty * 8 + r;
        float4 v = make_float4(acc[r][0], acc[r][1], acc[r][2], acc[r][3]);
        *(float4*)&d_lit[side][(size_t)row * Eq + tx * 4] = v;
        float4 rv = make_float4(fmaxf(v.x, 0.f), fmaxf(v.y, 0.f), fmaxf(v.z, 0.f), fmaxf(v.w, 0.f));
        *(float4*)&d_emb[side * 2 + 0][(size_t)row * Eq + tx * 4] = rv;
        *(float4*)&d_emb[side * 2 + 1][(size_t)row * Eq + tx * 4] = rv;
        float4 tv = make_float4(tf32f(rv.x), tf32f(rv.y), tf32f(rv.z), tf32f(rv.w));
        *(float4*)&d_embt[side * 2 + 0][(size_t)row * Eq + tx * 4] = tv;
        *(float4*)&d_embt[side * 2 + 1][(size_t)row * Eq + tx * 4] = tv;
    }
}

// ---------------- K3: XZ = SEMANTIC @ gru_k + b_i ----------------
__global__ void k_xz(const float* __restrict__ sem1, const float* __restrict__ sem2,
                     const float* __restrict__ k1, const float* __restrict__ k2,
                     const float* __restrict__ gb1, const float* __restrict__ gb2) {
    extern __shared__ float sm[];
    float* Ws = sm;
    float* Xs = sm + Eq * Eq;
    int side = blockIdx.x >> 5;
    int tile = blockIdx.x & 31;
    int tid = threadIdx.x;
    const float* K = side ? k2 : k1;
    const float* BI = side ? gb2 : gb1;
    const float* X = (side ? sem2 : sem1) + (size_t)tile * 64 * Eq;
    {
        float4* x4 = (float4*)Xs; const float4* h4 = (const float4*)X;
        for (int i = tid; i < 64 * Eq / 4; i += 256) x4[i] = h4[i];
    }
    int tx = tid & 31, ty = tid >> 5;
    for (int ch = 0; ch < 3; ch++) {
        __syncthreads();
        for (int i = tid; i < Eq * Eq; i += 256) {
            int kk = i >> 7; int cc = i & 127;
            Ws[i] = K[kk * 384 + ch * 128 + cc];
        }
        __syncthreads();
        float acc[8][4];
#pragma unroll
        for (int r = 0; r < 8; r++)
#pragma unroll
            for (int c = 0; c < 4; c++) acc[r][c] = 0.f;
        MAC_64x128(Xs, Ws, acc, tx, ty);
        float4 bi = *(const float4*)&BI[ch * 128 + tx * 4];
#pragma unroll
        for (int r = 0; r < 8; r++) {
            int row = tile * 64 + ty * 8 + r;
            float4 v = make_float4(acc[r][0] + bi.x, acc[r][1] + bi.y,
                                   acc[r][2] + bi.z, acc[r][3] + bi.w);
            *(float4*)&d_xz[side][(size_t)row * 384 + ch * 128 + tx * 4] = v;
        }
    }
}

// ---------------- K4: GRU recurrence (4 independent accumulators) ----------------
__global__ void k_gru(const float* __restrict__ rk1, const float* __restrict__ rk2,
                      const float* __restrict__ gb1, const float* __restrict__ gb2) {
    extern __shared__ float sm[];
    float* rks = sm;             // [128*384]
    float* hs = sm + 128 * 384;  // [128]
    float* hzs = hs + 128;       // [384]
    float* brs = hzs + 384;      // [384]
    int side = blockIdx.x >> 5;
    int b = blockIdx.x & 31;
    int tid = threadIdx.x;
    const float* rk = side ? rk2 : rk1;
    const float* GB = side ? gb2 : gb1;
    for (int i = tid; i < 128 * 384; i += 384) rks[i] = rk[i];
    brs[tid] = GB[384 + tid];
    if (tid < 128) hs[tid] = 0.f;
    __syncthreads();

    for (int t = 0; t < Tq; t++) {
        const float* xzr = d_xz[side] + ((size_t)(b * Tq + t)) * 384;
        float a0 = brs[tid], a1 = 0.f, a2 = 0.f, a3 = 0.f;
#pragma unroll
        for (int q = 0; q < 32; q += 4) {
            float4 h0 = *(const float4*)&hs[q * 4];
            float4 h1 = *(const float4*)&hs[q * 4 + 4];
            float4 h2 = *(const float4*)&hs[q * 4 + 8];
            float4 h3 = *(const float4*)&hs[q * 4 + 12];
            const float* rp = rks + q * 4 * 384 + tid;
            a0 = fmaf(h0.x, rp[0 * 384], a0);
            a0 = fmaf(h0.y, rp[1 * 384], a0);
            a0 = fmaf(h0.z, rp[2 * 384], a0);
            a0 = fmaf(h0.w, rp[3 * 384], a0);
            a1 = fmaf(h1.x, rp[4 * 384], a1);
            a1 = fmaf(h1.y, rp[5 * 384], a1);
            a1 = fmaf(h1.z, rp[6 * 384], a1);
            a1 = fmaf(h1.w, rp[7 * 384], a1);
            a2 = fmaf(h2.x, rp[8 * 384], a2);
            a2 = fmaf(h2.y, rp[9 * 384], a2);
            a2 = fmaf(h2.z, rp[10 * 384], a2);
            a2 = fmaf(h2.w, rp[11 * 384], a2);
            a3 = fmaf(h3.x, rp[12 * 384], a3);
            a3 = fmaf(h3.y, rp[13 * 384], a3);
            a3 = fmaf(h3.z, rp[14 * 384], a3);
            a3 = fmaf(h3.w, rp[15 * 384], a3);
        }
        hzs[tid] = (a0 + a1) + (a2 + a3);
        __syncthreads();
        if (tid < 128) {
            float z = fsigmoid(xzr[tid] + hzs[tid]);
            float r = fsigmoid(xzr[128 + tid] + hzs[128 + tid]);
            float hh = ftanh(xzr[256 + tid] + r * hzs[256 + tid]);
            hs[tid] = z * hs[tid] + (1.f - z) * hh;
        }
        __syncthreads();
    }
    if (tid < 128) d_sem[side][b * Eq + tid] = hs[tid];
}

// ---------------- K5: attention scores h1,h2 ----------------
__global__ void k_scores(const float* __restrict__ cw1, const float* __restrict__ cb1,
                         const float* __restrict__ cw2, const float* __restrict__ cb2,
                         const float* __restrict__ lw1, const float* __restrict__ lb1,
                         const float* __restrict__ lw2, const float* __restrict__ lb2) {
    __shared__ float w1s[Eq], w2s[Eq];
    int s = blockIdx.x >> 6;
    int bn = (blockIdx.x & 63) * 256 + threadIdx.x;
    const float* w1 = (s & 1) ? lw1 : cw1;
    const float* w2 = (s & 1) ? lw2 : cw2;
    float b1 = ((s & 1) ? lb1 : cb1)[0];
    float b2 = ((s & 1) ? lb2 : cb2)[0];
    if (threadIdx.x < Eq) { w1s[threadIdx.x] = w1[threadIdx.x]; w2s[threadIdx.x] = w2[threadIdx.x]; }
    __syncthreads();
    const float4* er = (const float4*)(d_emb[s] + (size_t)bn * Eq);
    float s1 = 0.f, s2 = 0.f;
#pragma unroll
    for (int k = 0; k < 32; k++) {
        float4 v = er[k];
        s1 += v.x * w1s[4 * k] + v.y * w1s[4 * k + 1] + v.z * w1s[4 * k + 2] + v.w * w1s[4 * k + 3];
        s2 += v.x * w2s[4 * k] + v.y * w2s[4 * k + 1] + v.z * w2s[4 * k + 2] + v.w * w2s[4 * k + 3];
    }
    d_h1[s][bn] = s1 + b1;
    d_h2[s][bn] = s2 + b2;
}

// ---------------- K6: per-row softmax stats ----------------
__global__ void k_stats() {
    __shared__ float h2s[Nq];
    int s = blockIdx.x >> 5;
    int b = blockIdx.x & 31;
    int i = threadIdx.x;
    h2s[i] = d_h2[s][b * Nq + i];
    __syncthreads();
    float h1i = d_h1[s][b * Nq + i];
    const unsigned* gr = &d_gb[s][(size_t)(b * Nq + i) * NWORD];
    float m = -1e30f;
#pragma unroll 4
    for (int w = 0; w < NWORD; w++) {
        unsigned bits = gr[w];
        for (int j2 = 0; j2 < 32; j2++)
            if ((bits >> j2) & 1u) m = fmaxf(m, lrelu(h1i + h2s[w * 32 + j2]));
    }
    float z = 0.f;
    if (m > -1e29f) {
#pragma unroll 4
        for (int w = 0; w < NWORD; w++) {
            unsigned bits = gr[w];
            for (int j2 = 0; j2 < 32; j2++)
                if ((bits >> j2) & 1u) z += __expf(lrelu(h1i + h2s[w * 32 + j2]) - m);
        }
        d_mx[s][b * Nq + i] = m;
        d_iz[s][b * Nq + i] = __fdividef(1.f, z);
    } else {
        d_mx[s][b * Nq + i] = 0.f;
        d_iz[s][b * Nq + i] = 0.f;
    }
}

// ---------------- K7: fused attention apply (tf32 mma) ----------------
constexpr int EJS = 136;   // embJ stride (B operand: ≡8 mod 32)
constexpr int ASS = 68;    // aS stride   (A operand: ≡4 mod 32)
__global__ void k_av() {
    extern __shared__ float sm[];
    float* embJ = sm;                       // [64][136]
    float* aS = embJ + 64 * EJS;            // [64][68]
    float* h1s = aS + 64 * ASS;
    float* ms = h1s + 64;
    float* izs = ms + 64;
    float* h2s = izs + 64;
    unsigned* gbs = (unsigned*)(h2s + 64);  // [128]

    int bx = blockIdx.x;
    int s = bx >> 8;
    int rem = bx & 255;
    int b = rem >> 3;
    int it = rem & 7;
    int i0 = it * 64;
    int tid = threadIdx.x;
    int w = tid >> 5, lane = tid & 31;
    int wm = w >> 1, wn = w & 1;
    int mr = wm * 16, cn = wn * 64;
    int g = lane >> 2, tg = lane & 3;

    if (tid < 64) {
        int row = b * Nq + i0 + tid;
        h1s[tid] = d_h1[s][row];
        ms[tid] = d_mx[s][row];
        izs[tid] = d_iz[s][row];
    }

    float acc[8][4];
#pragma unroll
    for (int r = 0; r < 8; r++)
#pragma unroll
        for (int c = 0; c < 4; c++) acc[r][c] = 0.f;

    for (int jt = 0; jt < 8; jt++) {
        int j0 = jt * 64;
        __syncthreads();
        {
            const float* src = d_embt[s] + (size_t)(b * Nq + j0) * Eq;
            for (int q = tid; q < 64 * 32; q += 256) {
                int j = q >> 5, c4 = q & 31;
                *(float4*)&embJ[j * EJS + c4 * 4] = *(const float4*)&src[j * Eq + c4 * 4];
            }
        }
        if (tid < 64) h2s[tid] = d_h2[s][b * Nq + j0 + tid];
        if (tid < 128) {
            int row = tid >> 1, which = tid & 1;
            gbs[tid] = d_gb[s][(size_t)(b * Nq + i0 + row) * NWORD + jt * 2 + which];
        }
        __syncthreads();
        // build A tile (tf32-rounded)
        for (int q = tid; q < 64 * 64; q += 256) {
            int i = q >> 6, j = q & 63;
            unsigned bits = gbs[i * 2 + (j >> 5)];
            float a = 0.f;
            if ((bits >> (j & 31)) & 1u) {
                float lr = lrelu(h1s[i] + h2s[j]);
                a = __expf(lr - ms[i]) * izs[i];
            }
            aS[i * ASS + j] = tf32f(a);
        }
        __syncthreads();
        mma_mac<8, ASS, EJS>(aS, embJ, acc, mr, cn, g, tg);
    }
    // epilogue: c0,c1 at (mr+g, n+2tg), c2,c3 at (mr+g+8, n+2tg)
#pragma unroll
    for (int nt = 0; nt < 8; nt++) {
        int n = cn + nt * 8;
        size_t r0 = (size_t)(b * Nq + i0 + mr + g) * Eq + n + 2 * tg;
        size_t r1 = (size_t)(b * Nq + i0 + mr + g + 8) * Eq + n + 2 * tg;
        *(float2*)&d_new[s][r0] = make_float2(acc[nt][0], acc[nt][1]);
        *(float2*)&d_new[s][r1] = make_float2(acc[nt][2], acc[nt][3]);
    }
}

// ---------------- K8: fused MLP (tf32 mma): emb = tanh(lit + relu(new@W1)@W2) ---
constexpr int XSS = 132;   // Xs stride (A operand)
constexpr int WSS = 136;   // Ws stride (B operand)
__global__ void k_mlp(const float* __restrict__ W1, const float* __restrict__ W2) {
    extern __shared__ float sm[];
    float* Xs = sm;                // [64][132]
    float* Ws = sm + 64 * XSS;     // [128][136]
    int tile = blockIdx.x;
    int tid = threadIdx.x;
    int w = tid >> 5, lane = tid & 31;
    int wm = w >> 1, wn = w & 1;
    int mr = wm * 16, cn = wn * 64;
    int g = lane >> 2, tg = lane & 3;

    const float* X = &d_new[0][0] + (size_t)tile * 64 * Eq;
    for (int q = tid; q < 64 * 32; q += 256) {
        int r = q >> 5, c4 = q & 31;
        float4 v = *(const float4*)&X[r * Eq + c4 * 4];
        *(float4*)&Xs[r * XSS + c4 * 4] =
            make_float4(tf32f(v.x), tf32f(v.y), tf32f(v.z), tf32f(v.w));
    }
    for (int q = tid; q < 128 * 32; q += 256) {
        int k = q >> 5, c4 = q & 31;
        float4 v = *(const float4*)&W1[k * Eq + c4 * 4];
        *(float4*)&Ws[k * WSS + c4 * 4] =
            make_float4(tf32f(v.x), tf32f(v.y), tf32f(v.z), tf32f(v.w));
    }
    __syncthreads();

    float acc[8][4];
#pragma unroll
    for (int r = 0; r < 8; r++)
#pragma unroll
        for (int c = 0; c < 4; c++) acc[r][c] = 0.f;
    mma_mac<16, XSS, WSS>(Xs, Ws, acc, mr, cn, g, tg);
    __syncthreads();   // all reads of Xs/Ws(W1) done

    // store relu(T) (tf32) back into Xs; load W2
#pragma unroll
    for (int nt = 0; nt < 8; nt++) {
        int n = cn + nt * 8;
        Xs[(mr + g) * XSS + n + 2 * tg]     = tf32f(fmaxf(acc[nt][0], 0.f));
        Xs[(mr + g) * XSS + n + 2 * tg + 1] = tf32f(fmaxf(acc[nt][1], 0.f));
        Xs[(mr + g + 8) * XSS + n + 2 * tg]     = tf32f(fmaxf(acc[nt][2], 0.f));
        Xs[(mr + g + 8) * XSS + n + 2 * tg + 1] = tf32f(fmaxf(acc[nt][3], 0.f));
    }
    for (int q = tid; q < 128 * 32; q += 256) {
        int k = q >> 5, c4 = q & 31;
        float4 v = *(const float4*)&W2[k * Eq + c4 * 4];
        *(float4*)&Ws[k * WSS + c4 * 4] =
            make_float4(tf32f(v.x), tf32f(v.y), tf32f(v.z), tf32f(v.w));
    }
    __syncthreads();

#pragma unroll
    for (int r = 0; r < 8; r++)
#pragma unroll
        for (int c = 0; c < 4; c++) acc[r][c] = 0.f;
    mma_mac<16, XSS, WSS>(Xs, Ws, acc, mr, cn, g, tg);

    int s = (tile * 64) / BN;
    int side = s >> 1;
    int rbase = tile * 64 - s * BN;
#pragma unroll
    for (int nt = 0; nt < 8; nt++) {
        int n = cn + nt * 8;
#pragma unroll
        for (int hh = 0; hh < 2; hh++) {
            int rloc = mr + g + hh * 8;
            int row = rbase + rloc;
            float2 lv = *(const float2*)&d_lit[side][(size_t)row * Eq + n + 2 * tg];
            float t0 = ftanh(lv.x + acc[nt][2 * hh + 0]);
            float t1 = ftanh(lv.y + acc[nt][2 * hh + 1]);
            size_t o = ((size_t)tile * 64 + rloc) * Eq + n + 2 * tg;
            *(float2*)&(&d_emb[0][0])[o] = make_float2(t0, t1);
            *(float2*)&(&d_embt[0][0])[o] = make_float2(tf32f(t0), tf32f(t1));
        }
    }
}

// ---------------- K10: mid = sum_N concat(cfg_e, lfg_e) ----------------
__global__ void k_colsum() {
    int side = blockIdx.x >> 5;
    int b = blockIdx.x & 31;
    int e2 = threadIdx.x;
    int st = side * 2 + (e2 >> 7);
    int e = e2 & 127;
    float sum = 0.f;
    const float* base = d_emb[st] + (size_t)b * Nq * Eq + e;
    for (int i = 0; i < Nq; i++) sum += base[(size_t)i * Eq];
    d_mid[side][b * 256 + e2] = sum;
}

// ---------------- K11: output head + cosine ----------------
__global__ void k_final(const float* __restrict__ Wout, const float* __restrict__ bout,
                        float* __restrict__ out) {
    int b = blockIdx.x;
    int o = threadIdx.x;
    float e[2];
#pragma unroll
    for (int side = 0; side < 2; side++) {
        float a = bout[o];
        const float* mid = d_mid[side] + b * 256;
        for (int k = 0; k < 256; k++) a = fmaf(mid[k], Wout[k * Oq + o], a);
        const float* se = d_sem[side] + b * Eq;
        for (int k = 0; k < 128; k++) a = fmaf(se[k], Wout[(256 + k) * Oq + o], a);
        e[side] = a;
    }
    float p = e[0] * e[1], q0 = e[0] * e[0], q1 = e[1] * e[1];
#pragma unroll
    for (int off = 16; off; off >>= 1) {
        p += __shfl_xor_sync(0xffffffffu, p, off);
        q0 += __shfl_xor_sync(0xffffffffu, q0, off);
        q1 += __shfl_xor_sync(0xffffffffu, q1, off);
    }
    __shared__ float sp[2], s0[2], s1[2];
    if ((o & 31) == 0) { int w = o >> 5; sp[w] = p; s0[w] = q0; s1[w] = q1; }
    __syncthreads();
    if (o == 0) {
        float dot = sp[0] + sp[1];
        float n0 = s0[0] + s0[1];
        float n1 = s1[0] + s1[1];
        out[b] = 0.5f * (1.f + dot * rsqrtf(fmaxf(n0, 1e-12f)) * rsqrtf(fmaxf(n1, 1e-12f)));
    }
}

// ---------------- host launcher ----------------
constexpr int GEMM_SMEM = (Eq * Eq + 64 * Eq) * 4;
constexpr int MLP_SMEM = (64 * XSS + 128 * WSS) * 4;            // 103424
constexpr int GRU_SMEM = (128 * 384 + 128 + 384 + 384) * 4;     // 200192
constexpr int AV_SMEM = (64 * EJS + 64 * ASS + 64 * 4) * 4 + 128 * 4;  // 53760

extern "C" void kernel_launch(void* const* d_in, const int* in_sizes, int n_in,
                              void* d_out, int out_size) {
    const int* CFG1 = (const int*)d_in[0];
    const int* LFG1 = (const int*)d_in[1];
    const float* LIT1 = (const float*)d_in[2];
    const float* SEM1 = (const float*)d_in[3];
    const int* CFG2 = (const int*)d_in[4];
    const int* LFG2 = (const int*)d_in[5];
    const float* LIT2 = (const float*)d_in[6];
    const float* SEM2 = (const float*)d_in[7];
    const float* Wlit1 = (const float*)d_in[8];
    const float* gk1 = (const float*)d_in[9];
    const float* grk1 = (const float*)d_in[10];
    const float* gb1 = (const float*)d_in[11];
    const float* Wlit2 = (const float*)d_in[12];
    const float* gk2 = (const float*)d_in[13];
    const float* grk2 = (const float*)d_in[14];
    const float* gb2 = (const float*)d_in[15];
    const float* ca1w = (const float*)d_in[16];
    const float* ca1b = (const float*)d_in[17];
    const float* ca2w = (const float*)d_in[18];
    const float* ca2b = (const float*)d_in[19];
    const float* la1w = (const float*)d_in[20];
    const float* la1b = (const float*)d_in[21];
    const float* la2w = (const float*)d_in[22];
    const float* la2b = (const float*)d_in[23];
    const float* mlp1 = (const float*)d_in[24];
    const float* mlp2 = (const float*)d_in[25];
    const float* Wout = (const float*)d_in[26];
    const float* bout = (const float*)d_in[27];
    float* out = (float*)d_out;

    cudaFuncSetAttribute(k_lit, cudaFuncAttributeMaxDynamicSharedMemorySize, GEMM_SMEM);
    cudaFuncSetAttribute(k_xz, cudaFuncAttributeMaxDynamicSharedMemorySize, GEMM_SMEM);
    cudaFuncSetAttribute(k_gru, cudaFuncAttributeMaxDynamicSharedMemorySize, GRU_SMEM);
    cudaFuncSetAttribute(k_av, cudaFuncAttributeMaxDynamicSharedMemorySize, AV_SMEM);
    cudaFuncSetAttribute(k_mlp, cudaFuncAttributeMaxDynamicSharedMemorySize, MLP_SMEM);

    k_pack<<<4 * BN * NWORD / 256, 256>>>(CFG1, LFG1, CFG2, LFG2);
    k_lit<<<512, 256, GEMM_SMEM>>>(LIT1, LIT2, Wlit1, Wlit2);
    k_xz<<<64, 256, GEMM_SMEM>>>(SEM1, SEM2, gk1, gk2, gb1, gb2);
    k_gru<<<64, 384, GRU_SMEM>>>(grk1, grk2, gb1, gb2);

    for (int it = 0; it < N_ITERS; it++) {
        k_scores<<<256, 256>>>(ca1w, ca1b, ca2w, ca2b, la1w, la1b, la2w, la2b);
        k_stats<<<128, 512>>>();
        k_av<<<NSTREAM * Bq * 8, 256, AV_SMEM>>>();
        k_mlp<<<1024, 256, MLP_SMEM>>>(mlp1, mlp2);
    }
    k_colsum<<<64, 256>>>();
    k_final<<<32, 64>>>(Wout, bout, out);
}

// round 4
// speedup vs baseline: 3.2447x; 1.0922x over previous
#include <cuda_runtime.h>

#define DEV_INLINE __device__ __forceinline__

// ---------------- problem constants ----------------
constexpr int Bq = 32;
constexpr int Nq = 512;
constexpr int Tq = 64;
constexpr int Eq = 128;
constexpr int Oq = 64;
constexpr int NSTREAM = 4;
constexpr int BN = Bq * Nq;
constexpr int NWORD = Nq / 32;
constexpr int N_ITERS = 5;

// ---------------- device scratch ----------------
__device__ __align__(128) float d_lit[2][BN * Eq];
__device__ __align__(128) float d_emb[NSTREAM][BN * Eq];
__device__ __align__(128) float d_new[NSTREAM][BN * Eq];
__device__ __align__(128) unsigned d_gb[NSTREAM][BN * NWORD];
__device__ __align__(128) float d_h1[NSTREAM][BN];
__device__ __align__(128) float d_h2[NSTREAM][BN];
__device__ __align__(128) float d_mx[NSTREAM][BN];
__device__ __align__(128) float d_iz[NSTREAM][BN];
__device__ __align__(128) float d_xz[2][Bq * Tq * 3 * Eq];
__device__ __align__(128) float d_sem[2][Bq * Eq];
__device__ __align__(128) float d_mid[2][Bq * 2 * Eq];

// ---------------- helpers ----------------
DEV_INLINE float lrelu(float x) { return x > 0.f ? x : 0.2f * x; }
DEV_INLINE float fsigmoid(float x) { return __fdividef(1.f, 1.f + __expf(-x)); }
DEV_INLINE float ftanh(float x) {
    float e = __expf(2.f * x);
    return 1.f - __fdividef(2.f, e + 1.f);
}

// ---------------- K1: pack 0/1 int graphs into bitmasks ----------------
__global__ void k_pack(const int* __restrict__ c1, const int* __restrict__ l1,
                       const int* __restrict__ c2, const int* __restrict__ l2) {
    int idx = blockIdx.x * blockDim.x + threadIdx.x;
    int w = idx & (NWORD - 1);
    int row = idx >> 4;
    int s = row / BN;
    int bn = row - s * BN;
    const int* src = (s == 0) ? c1 : (s == 1) ? l1 : (s == 2) ? c2 : l2;
    src += (size_t)bn * Nq + w * 32;
    unsigned bits = 0u;
#pragma unroll
    for (int j4 = 0; j4 < 8; j4++) {
        int4 v = ((const int4*)src)[j4];
        bits |= (v.x != 0 ? 1u : 0u) << (4 * j4);
        bits |= (v.y != 0 ? 1u : 0u) << (4 * j4 + 1);
        bits |= (v.z != 0 ? 1u : 0u) << (4 * j4 + 2);
        bits |= (v.w != 0 ? 1u : 0u) << (4 * j4 + 3);
    }
    d_gb[s][bn * NWORD + w] = bits;
}

// ======== scalar register-blocked MAC (setup GEMMs) ========
#define MAC_64x128(Xs, Ws, acc, tx, ty)                                          \
    {                                                                            \
        _Pragma("unroll 4") for (int k = 0; k < Eq; k++) {                       \
            float4 wv = *(const float4*)&(Ws)[k * Eq + (tx) * 4];                \
            float xr[8];                                                         \
            _Pragma("unroll") for (int r = 0; r < 8; r++)                        \
                xr[r] = (Xs)[((ty) * 8 + r) * Eq + k];                           \
            _Pragma("unroll") for (int r = 0; r < 8; r++) {                      \
                acc[r][0] = fmaf(xr[r], wv.x, acc[r][0]);                        \
                acc[r][1] = fmaf(xr[r], wv.y, acc[r][1]);                        \
                acc[r][2] = fmaf(xr[r], wv.z, acc[r][2]);                        \
                acc[r][3] = fmaf(xr[r], wv.w, acc[r][3]);                        \
            }                                                                    \
        }                                                                        \
    }

// ---------------- K2: lit = LITERAL @ W_lit ; emb = relu(lit) ----------------
__global__ void k_lit(const float* __restrict__ lit1, const float* __restrict__ lit2,
                      const float* __restrict__ w1, const float* __restrict__ w2) {
    extern __shared__ float sm[];
    float* Ws = sm;
    float* Xs = sm + Eq * Eq;
    int side = blockIdx.x >> 8;
    int tile = blockIdx.x & 255;
    int tid = threadIdx.x;
    const float* W = side ? w2 : w1;
    const float* X = (side ? lit2 : lit1) + (size_t)tile * 64 * Eq;
    {
        float4* w4 = (float4*)Ws; const float4* g4 = (const float4*)W;
        for (int i = tid; i < Eq * Eq / 4; i += 256) w4[i] = g4[i];
        float4* x4 = (float4*)Xs; const float4* h4 = (const float4*)X;
        for (int i = tid; i < 64 * Eq / 4; i += 256) x4[i] = h4[i];
    }
    __syncthreads();
    int tx = tid & 31, ty = tid >> 5;
    float acc[8][4];
#pragma unroll
    for (int r = 0; r < 8; r++)
#pragma unroll
        for (int c = 0; c < 4; c++) acc[r][c] = 0.f;
    MAC_64x128(Xs, Ws, acc, tx, ty);
#pragma unroll
    for (int r = 0; r < 8; r++) {
        int row = tile * 64 + ty * 8 + r;
        float4 v = make_float4(acc[r][0], acc[r][1], acc[r][2], acc[r][3]);
        *(float4*)&d_lit[side][(size_t)row * Eq + tx * 4] = v;
        float4 rv = make_float4(fmaxf(v.x, 0.f), fmaxf(v.y, 0.f), fmaxf(v.z, 0.f), fmaxf(v.w, 0.f));
        *(float4*)&d_emb[side * 2 + 0][(size_t)row * Eq + tx * 4] = rv;
        *(float4*)&d_emb[side * 2 + 1][(size_t)row * Eq + tx * 4] = rv;
    }
}

// ---------------- K3: XZ = SEMANTIC @ gru_k + b_i ----------------
__global__ void k_xz(const float* __restrict__ sem1, const float* __restrict__ sem2,
                     const float* __restrict__ k1, const float* __restrict__ k2,
                     const float* __restrict__ gb1, const float* __restrict__ gb2) {
    extern __shared__ float sm[];
    float* Ws = sm;
    float* Xs = sm + Eq * Eq;
    int side = blockIdx.x >> 5;
    int tile = blockIdx.x & 31;
    int tid = threadIdx.x;
    const float* K = side ? k2 : k1;
    const float* BI = side ? gb2 : gb1;
    const float* X = (side ? sem2 : sem1) + (size_t)tile * 64 * Eq;
    {
        float4* x4 = (float4*)Xs; const float4* h4 = (const float4*)X;
        for (int i = tid; i < 64 * Eq / 4; i += 256) x4[i] = h4[i];
    }
    int tx = tid & 31, ty = tid >> 5;
    for (int ch = 0; ch < 3; ch++) {
        __syncthreads();
        for (int i = tid; i < Eq * Eq; i += 256) {
            int kk = i >> 7; int cc = i & 127;
            Ws[i] = K[kk * 384 + ch * 128 + cc];
        }
        __syncthreads();
        float acc[8][4];
#pragma unroll
        for (int r = 0; r < 8; r++)
#pragma unroll
            for (int c = 0; c < 4; c++) acc[r][c] = 0.f;
        MAC_64x128(Xs, Ws, acc, tx, ty);
        float4 bi = *(const float4*)&BI[ch * 128 + tx * 4];
#pragma unroll
        for (int r = 0; r < 8; r++) {
            int row = tile * 64 + ty * 8 + r;
            float4 v = make_float4(acc[r][0] + bi.x, acc[r][1] + bi.y,
                                   acc[r][2] + bi.z, acc[r][3] + bi.w);
            *(float4*)&d_xz[side][(size_t)row * 384 + ch * 128 + tx * 4] = v;
        }
    }
}

// ---------------- K4: GRU recurrence (register-resident rk) ----------------
__global__ __launch_bounds__(384, 1)
void k_gru(const float* __restrict__ rk1, const float* __restrict__ rk2,
           const float* __restrict__ gb1, const float* __restrict__ gb2) {
    __shared__ float hs[128];
    __shared__ float hzs[384];
    int side = blockIdx.x >> 5;
    int b = blockIdx.x & 31;
    int tid = threadIdx.x;            // = n column in [0,384)
    const float* rk = side ? rk2 : rk1;
    const float* GB = side ? gb2 : gb1;

    // own one column of rk in registers
    float rkr[128];
#pragma unroll
    for (int d = 0; d < 128; d++) rkr[d] = rk[d * 384 + tid];
    float brv = GB[384 + tid];
    if (tid < 128) hs[tid] = 0.f;
    __syncthreads();

    const float* xzb = d_xz[side] + (size_t)(b * Tq) * 384;
    for (int t = 0; t < Tq; t++) {
        // prefetch gate inputs for this timestep (consumed after barrier)
        float xz0 = 0.f, xz1 = 0.f, xz2 = 0.f;
        if (tid < 128) {
            const float* xzr = xzb + (size_t)t * 384;
            xz0 = xzr[tid];
            xz1 = xzr[128 + tid];
            xz2 = xzr[256 + tid];
        }
        float a0 = brv, a1 = 0.f, a2 = 0.f, a3 = 0.f;
#pragma unroll
        for (int d = 0; d < 128; d += 4) {
            float4 h4 = *(const float4*)&hs[d];
            a0 = fmaf(h4.x, rkr[d], a0);
            a1 = fmaf(h4.y, rkr[d + 1], a1);
            a2 = fmaf(h4.z, rkr[d + 2], a2);
            a3 = fmaf(h4.w, rkr[d + 3], a3);
        }
        hzs[tid] = (a0 + a1) + (a2 + a3);
        __syncthreads();
        if (tid < 128) {
            float z = fsigmoid(xz0 + hzs[tid]);
            float r = fsigmoid(xz1 + hzs[128 + tid]);
            float hh = ftanh(xz2 + r * hzs[256 + tid]);
            hs[tid] = z * hs[tid] + (1.f - z) * hh;
        }
        __syncthreads();
    }
    if (tid < 128) d_sem[side][b * Eq + tid] = hs[tid];
}

// ---------------- K5: attention scores h1,h2 ----------------
__global__ void k_scores(const float* __restrict__ cw1, const float* __restrict__ cb1,
                         const float* __restrict__ cw2, const float* __restrict__ cb2,
                         const float* __restrict__ lw1, const float* __restrict__ lb1,
                         const float* __restrict__ lw2, const float* __restrict__ lb2) {
    __shared__ float w1s[Eq], w2s[Eq];
    int s = blockIdx.x >> 6;
    int bn = (blockIdx.x & 63) * 256 + threadIdx.x;
    const float* w1 = (s & 1) ? lw1 : cw1;
    const float* w2 = (s & 1) ? lw2 : cw2;
    float b1 = ((s & 1) ? lb1 : cb1)[0];
    float b2 = ((s & 1) ? lb2 : cb2)[0];
    if (threadIdx.x < Eq) { w1s[threadIdx.x] = w1[threadIdx.x]; w2s[threadIdx.x] = w2[threadIdx.x]; }
    __syncthreads();
    const float4* er = (const float4*)(d_emb[s] + (size_t)bn * Eq);
    float s1 = 0.f, s2 = 0.f;
#pragma unroll
    for (int k = 0; k < 32; k++) {
        float4 v = er[k];
        s1 += v.x * w1s[4 * k] + v.y * w1s[4 * k + 1] + v.z * w1s[4 * k + 2] + v.w * w1s[4 * k + 3];
        s2 += v.x * w2s[4 * k] + v.y * w2s[4 * k + 1] + v.z * w2s[4 * k + 2] + v.w * w2s[4 * k + 3];
    }
    d_h1[s][bn] = s1 + b1;
    d_h2[s][bn] = s2 + b2;
}

// ---------------- K6: per-row softmax stats ----------------
__global__ void k_stats() {
    __shared__ float h2s[Nq];
    int s = blockIdx.x >> 5;
    int b = blockIdx.x & 31;
    int i = threadIdx.x;
    h2s[i] = d_h2[s][b * Nq + i];
    __syncthreads();
    float h1i = d_h1[s][b * Nq + i];
    const unsigned* gr = &d_gb[s][(size_t)(b * Nq + i) * NWORD];
    float m = -1e30f;
#pragma unroll 4
    for (int w = 0; w < NWORD; w++) {
        unsigned bits = gr[w];
        for (int j2 = 0; j2 < 32; j2++)
            if ((bits >> j2) & 1u) m = fmaxf(m, lrelu(h1i + h2s[w * 32 + j2]));
    }
    float z = 0.f;
    if (m > -1e29f) {
#pragma unroll 4
        for (int w = 0; w < NWORD; w++) {
            unsigned bits = gr[w];
            for (int j2 = 0; j2 < 32; j2++)
                if ((bits >> j2) & 1u) z += __expf(lrelu(h1i + h2s[w * 32 + j2]) - m);
        }
        d_mx[s][b * Nq + i] = m;
        d_iz[s][b * Nq + i] = __fdividef(1.f, z);
    } else {
        d_mx[s][b * Nq + i] = 0.f;
        d_iz[s][b * Nq + i] = 0.f;
    }
}

// ---------------- K7: fused attention apply (tf32 mma, 128-row i-tiles) -------
constexpr int EJS = 136;   // embJ stride (B operand: ≡8 mod 32)
constexpr int ASS = 68;    // aS stride   (A operand: ≡4 mod 32)
__global__ void k_av() {
    extern __shared__ float sm[];
    float* embJ = sm;                       // [64][136]
    float* aS = embJ + 64 * EJS;            // [128][68]
    float* h1s = aS + 128 * ASS;            // [128]
    float* ms = h1s + 128;                  // [128]
    float* izs = ms + 128;                  // [128]
    float* h2s = izs + 128;                 // [64]
    unsigned* gbs = (unsigned*)(h2s + 64);  // [256]

    int bx = blockIdx.x;
    int s = bx >> 7;
    int rem = bx & 127;
    int b = rem >> 2;
    int it = rem & 3;
    int i0 = it * 128;
    int tid = threadIdx.x;
    int w = tid >> 5, lane = tid & 31;
    int mr = w * 16;                 // warp owns 16 rows x 128 cols
    int g = lane >> 2, tg = lane & 3;

    if (tid < 128) {
        int row = b * Nq + i0 + tid;
        h1s[tid] = d_h1[s][row];
        ms[tid] = d_mx[s][row];
        izs[tid] = d_iz[s][row];
    }

    float acc[16][4];
#pragma unroll
    for (int r = 0; r < 16; r++)
#pragma unroll
        for (int c = 0; c < 4; c++) acc[r][c] = 0.f;

    for (int jt = 0; jt < 8; jt++) {
        int j0 = jt * 64;
        __syncthreads();
        {
            const float* src = d_emb[s] + (size_t)(b * Nq + j0) * Eq;
            for (int q = tid; q < 64 * 32; q += 256) {
                int j = q >> 5, c4 = q & 31;
                *(float4*)&embJ[j * EJS + c4 * 4] = *(const float4*)&src[j * Eq + c4 * 4];
            }
        }
        if (tid < 64) h2s[tid] = d_h2[s][b * Nq + j0 + tid];
        {
            int row = tid >> 1, which = tid & 1;
            gbs[tid] = d_gb[s][(size_t)(b * Nq + i0 + row) * NWORD + jt * 2 + which];
        }
        __syncthreads();
        // build A tile (raw fp32; tf32 mma hardware truncates mantissa)
        for (int q = tid; q < 128 * 64; q += 256) {
            int i = q >> 6, j = q & 63;
            unsigned bits = gbs[i * 2 + (j >> 5)];
            float a = 0.f;
            if ((bits >> (j & 31)) & 1u) {
                float lr = lrelu(h1s[i] + h2s[j]);
                a = __expf(lr - ms[i]) * izs[i];
            }
            aS[i * ASS + j] = a;
        }
        __syncthreads();
#pragma unroll
        for (int ks = 0; ks < 8; ks++) {
            int k0 = ks * 8;
            unsigned a0 = __float_as_uint(aS[(mr + g) * ASS + k0 + tg]);
            unsigned a1 = __float_as_uint(aS[(mr + g + 8) * ASS + k0 + tg]);
            unsigned a2 = __float_as_uint(aS[(mr + g) * ASS + k0 + tg + 4]);
            unsigned a3 = __float_as_uint(aS[(mr + g + 8) * ASS + k0 + tg + 4]);
#pragma unroll
            for (int nt = 0; nt < 16; nt++) {
                int n = nt * 8;
                unsigned b0 = __float_as_uint(embJ[(k0 + tg) * EJS + n + g]);
                unsigned b1 = __float_as_uint(embJ[(k0 + tg + 4) * EJS + n + g]);
                asm("mma.sync.aligned.m16n8k8.row.col.f32.tf32.tf32.f32 "
                    "{%0,%1,%2,%3}, {%4,%5,%6,%7}, {%8,%9}, {%0,%1,%2,%3};"
                    : "+f"(acc[nt][0]), "+f"(acc[nt][1]), "+f"(acc[nt][2]), "+f"(acc[nt][3])
                    : "r"(a0), "r"(a1), "r"(a2), "r"(a3), "r"(b0), "r"(b1));
            }
        }
    }
#pragma unroll
    for (int nt = 0; nt < 16; nt++) {
        int n = nt * 8;
        size_t r0 = (size_t)(b * Nq + i0 + mr + g) * Eq + n + 2 * tg;
        size_t r1 = (size_t)(b * Nq + i0 + mr + g + 8) * Eq + n + 2 * tg;
        *(float2*)&d_new[s][r0] = make_float2(acc[nt][0], acc[nt][1]);
        *(float2*)&d_new[s][r1] = make_float2(acc[nt][2], acc[nt][3]);
    }
}

// ---------------- K8: fused MLP (tf32 mma): emb = tanh(lit + relu(new@W1)@W2) ---
constexpr int XSS = 132;   // Xs stride (A operand)
constexpr int WSS = 136;   // Ws stride (B operand)
__global__ void k_mlp(const float* __restrict__ W1, const float* __restrict__ W2) {
    extern __shared__ float sm[];
    float* Xs = sm;                // [64][132]
    float* Ws = sm + 64 * XSS;     // [128][136]
    int tile = blockIdx.x;
    int tid = threadIdx.x;
    int w = tid >> 5, lane = tid & 31;
    int wm = w >> 1, wn = w & 1;
    int mr = wm * 16, cn = wn * 64;
    int g = lane >> 2, tg = lane & 3;

    const float* X = &d_new[0][0] + (size_t)tile * 64 * Eq;
    for (int q = tid; q < 64 * 32; q += 256) {
        int r = q >> 5, c4 = q & 31;
        *(float4*)&Xs[r * XSS + c4 * 4] = *(const float4*)&X[r * Eq + c4 * 4];
    }
    for (int q = tid; q < 128 * 32; q += 256) {
        int k = q >> 5, c4 = q & 31;
        *(float4*)&Ws[k * WSS + c4 * 4] = *(const float4*)&W1[k * Eq + c4 * 4];
    }
    __syncthreads();

    float acc[8][4];
#pragma unroll
    for (int r = 0; r < 8; r++)
#pragma unroll
        for (int c = 0; c < 4; c++) acc[r][c] = 0.f;
#pragma unroll
    for (int ks = 0; ks < 16; ks++) {
        int k0 = ks * 8;
        unsigned a0 = __float_as_uint(Xs[(mr + g) * XSS + k0 + tg]);
        unsigned a1 = __float_as_uint(Xs[(mr + g + 8) * XSS + k0 + tg]);
        unsigned a2 = __float_as_uint(Xs[(mr + g) * XSS + k0 + tg + 4]);
        unsigned a3 = __float_as_uint(Xs[(mr + g + 8) * XSS + k0 + tg + 4]);
#pragma unroll
        for (int nt = 0; nt < 8; nt++) {
            int n = cn + nt * 8;
            unsigned b0 = __float_as_uint(Ws[(k0 + tg) * WSS + n + g]);
            unsigned b1 = __float_as_uint(Ws[(k0 + tg + 4) * WSS + n + g]);
            asm("mma.sync.aligned.m16n8k8.row.col.f32.tf32.tf32.f32 "
                "{%0,%1,%2,%3}, {%4,%5,%6,%7}, {%8,%9}, {%0,%1,%2,%3};"
                : "+f"(acc[nt][0]), "+f"(acc[nt][1]), "+f"(acc[nt][2]), "+f"(acc[nt][3])
                : "r"(a0), "r"(a1), "r"(a2), "r"(a3), "r"(b0), "r"(b1));
        }
    }
    __syncthreads();

    // store relu(T) back into Xs; load W2
#pragma unroll
    for (int nt = 0; nt < 8; nt++) {
        int n = cn + nt * 8;
        Xs[(mr + g) * XSS + n + 2 * tg]         = fmaxf(acc[nt][0], 0.f);
        Xs[(mr + g) * XSS + n + 2 * tg + 1]     = fmaxf(acc[nt][1], 0.f);
        Xs[(mr + g + 8) * XSS + n + 2 * tg]     = fmaxf(acc[nt][2], 0.f);
        Xs[(mr + g + 8) * XSS + n + 2 * tg + 1] = fmaxf(acc[nt][3], 0.f);
    }
    for (int q = tid; q < 128 * 32; q += 256) {
        int k = q >> 5, c4 = q & 31;
        *(float4*)&Ws[k * WSS + c4 * 4] = *(const float4*)&W2[k * Eq + c4 * 4];
    }
    __syncthreads();

#pragma unroll
    for (int r = 0; r < 8; r++)
#pragma unroll
        for (int c = 0; c < 4; c++) acc[r][c] = 0.f;
#pragma unroll
    for (int ks = 0; ks < 16; ks++) {
        int k0 = ks * 8;
        unsigned a0 = __float_as_uint(Xs[(mr + g) * XSS + k0 + tg]);
        unsigned a1 = __float_as_uint(Xs[(mr + g + 8) * XSS + k0 + tg]);
        unsigned a2 = __float_as_uint(Xs[(mr + g) * XSS + k0 + tg + 4]);
        unsigned a3 = __float_as_uint(Xs[(mr + g + 8) * XSS + k0 + tg + 4]);
#pragma unroll
        for (int nt = 0; nt < 8; nt++) {
            int n = cn + nt * 8;
            unsigned b0 = __float_as_uint(Ws[(k0 + tg) * WSS + n + g]);
            unsigned b1 = __float_as_uint(Ws[(k0 + tg + 4) * WSS + n + g]);
            asm("mma.sync.aligned.m16n8k8.row.col.f32.tf32.tf32.f32 "
                "{%0,%1,%2,%3}, {%4,%5,%6,%7}, {%8,%9}, {%0,%1,%2,%3};"
                : "+f"(acc[nt][0]), "+f"(acc[nt][1]), "+f"(acc[nt][2]), "+f"(acc[nt][3])
                : "r"(a0), "r"(a1), "r"(a2), "r"(a3), "r"(b0), "r"(b1));
        }
    }

    int s = (tile * 64) / BN;
    int side = s >> 1;
    int rbase = tile * 64 - s * BN;
#pragma unroll
    for (int nt = 0; nt < 8; nt++) {
        int n = cn + nt * 8;
#pragma unroll
        for (int hh = 0; hh < 2; hh++) {
            int rloc = mr + g + hh * 8;
            int row = rbase + rloc;
            float2 lv = *(const float2*)&d_lit[side][(size_t)row * Eq + n + 2 * tg];
            float t0 = ftanh(lv.x + acc[nt][2 * hh + 0]);
            float t1 = ftanh(lv.y + acc[nt][2 * hh + 1]);
            size_t o = ((size_t)tile * 64 + rloc) * Eq + n + 2 * tg;
            *(float2*)&(&d_emb[0][0])[o] = make_float2(t0, t1);
        }
    }
}

// ---------------- K10: mid = sum_N concat(cfg_e, lfg_e) ----------------
__global__ void k_colsum() {
    int side = blockIdx.x >> 5;
    int b = blockIdx.x & 31;
    int e2 = threadIdx.x;
    int st = side * 2 + (e2 >> 7);
    int e = e2 & 127;
    float sum = 0.f;
    const float* base = d_emb[st] + (size_t)b * Nq * Eq + e;
    for (int i = 0; i < Nq; i++) sum += base[(size_t)i * Eq];
    d_mid[side][b * 256 + e2] = sum;
}

// ---------------- K11: output head + cosine ----------------
__global__ void k_final(const float* __restrict__ Wout, const float* __restrict__ bout,
                        float* __restrict__ out) {
    int b = blockIdx.x;
    int o = threadIdx.x;
    float e[2];
#pragma unroll
    for (int side = 0; side < 2; side++) {
        float a = bout[o];
        const float* mid = d_mid[side] + b * 256;
        for (int k = 0; k < 256; k++) a = fmaf(mid[k], Wout[k * Oq + o], a);
        const float* se = d_sem[side] + b * Eq;
        for (int k = 0; k < 128; k++) a = fmaf(se[k], Wout[(256 + k) * Oq + o], a);
        e[side] = a;
    }
    float p = e[0] * e[1], q0 = e[0] * e[0], q1 = e[1] * e[1];
#pragma unroll
    for (int off = 16; off; off >>= 1) {
        p += __shfl_xor_sync(0xffffffffu, p, off);
        q0 += __shfl_xor_sync(0xffffffffu, q0, off);
        q1 += __shfl_xor_sync(0xffffffffu, q1, off);
    }
    __shared__ float sp[2], s0[2], s1[2];
    if ((o & 31) == 0) { int w = o >> 5; sp[w] = p; s0[w] = q0; s1[w] = q1; }
    __syncthreads();
    if (o == 0) {
        float dot = sp[0] + sp[1];
        float n0 = s0[0] + s0[1];
        float n1 = s1[0] + s1[1];
        out[b] = 0.5f * (1.f + dot * rsqrtf(fmaxf(n0, 1e-12f)) * rsqrtf(fmaxf(n1, 1e-12f)));
    }
}

// ---------------- host launcher ----------------
constexpr int GEMM_SMEM = (Eq * Eq + 64 * Eq) * 4;
constexpr int MLP_SMEM = (64 * XSS + 128 * WSS) * 4;                      // 103424
constexpr int AV_SMEM = (64 * EJS + 128 * ASS + 128 * 3 + 64) * 4 + 256 * 4;  // 72448

extern "C" void kernel_launch(void* const* d_in, const int* in_sizes, int n_in,
                              void* d_out, int out_size) {
    const int* CFG1 = (const int*)d_in[0];
    const int* LFG1 = (const int*)d_in[1];
    const float* LIT1 = (const float*)d_in[2];
    const float* SEM1 = (const float*)d_in[3];
    const int* CFG2 = (const int*)d_in[4];
    const int* LFG2 = (const int*)d_in[5];
    const float* LIT2 = (const float*)d_in[6];
    const float* SEM2 = (const float*)d_in[7];
    const float* Wlit1 = (const float*)d_in[8];
    const float* gk1 = (const float*)d_in[9];
    const float* grk1 = (const float*)d_in[10];
    const float* gb1 = (const float*)d_in[11];
    const float* Wlit2 = (const float*)d_in[12];
    const float* gk2 = (const float*)d_in[13];
    const float* grk2 = (const float*)d_in[14];
    const float* gb2 = (const float*)d_in[15];
    const float* ca1w = (const float*)d_in[16];
    const float* ca1b = (const float*)d_in[17];
    const float* ca2w = (const float*)d_in[18];
    const float* ca2b = (const float*)d_in[19];
    const float* la1w = (const float*)d_in[20];
    const float* la1b = (const float*)d_in[21];
    const float* la2w = (const float*)d_in[22];
    const float* la2b = (const float*)d_in[23];
    const float* mlp1 = (const float*)d_in[24];
    const float* mlp2 = (const float*)d_in[25];
    const float* Wout = (const float*)d_in[26];
    const float* bout = (const float*)d_in[27];
    float* out = (float*)d_out;

    cudaFuncSetAttribute(k_lit, cudaFuncAttributeMaxDynamicSharedMemorySize, GEMM_SMEM);
    cudaFuncSetAttribute(k_xz, cudaFuncAttributeMaxDynamicSharedMemorySize, GEMM_SMEM);
    cudaFuncSetAttribute(k_av, cudaFuncAttributeMaxDynamicSharedMemorySize, AV_SMEM);
    cudaFuncSetAttribute(k_mlp, cudaFuncAttributeMaxDynamicSharedMemorySize, MLP_SMEM);

    k_pack<<<4 * BN * NWORD / 256, 256>>>(CFG1, LFG1, CFG2, LFG2);
    k_lit<<<512, 256, GEMM_SMEM>>>(LIT1, LIT2, Wlit1, Wlit2);
    k_xz<<<64, 256, GEMM_SMEM>>>(SEM1, SEM2, gk1, gk2, gb1, gb2);
    k_gru<<<64, 384>>>(grk1, grk2, gb1, gb2);

    for (int it = 0; it < N_ITERS; it++) {
        k_scores<<<256, 256>>>(ca1w, ca1b, ca2w, ca2b, la1w, la1b, la2w, la2b);
        k_stats<<<128, 512>>>();
        k_av<<<NSTREAM * Bq * 4, 256, AV_SMEM>>>();
        k_mlp<<<1024, 256, MLP_SMEM>>>(mlp1, mlp2);
    }
    k_colsum<<<64, 256>>>();
    k_final<<<32, 64>>>(Wout, bout, out);
}

// round 5
// speedup vs baseline: 4.2844x; 1.3204x over previous
#include <cuda_runtime.h>

#define DEV_INLINE __device__ __forceinline__

// ---------------- problem constants ----------------
constexpr int Bq = 32;
constexpr int Nq = 512;
constexpr int Tq = 64;
constexpr int Eq = 128;
constexpr int Oq = 64;
constexpr int NSTREAM = 4;
constexpr int BN = Bq * Nq;
constexpr int NWORD = Nq / 32;
constexpr int N_ITERS = 5;

// ---------------- device scratch ----------------
__device__ __align__(128) float d_lit[2][BN * Eq];
__device__ __align__(128) float d_emb[NSTREAM][BN * Eq];
__device__ __align__(128) float d_new[NSTREAM][BN * Eq];
__device__ __align__(128) unsigned d_gb[NSTREAM][BN * NWORD];
__device__ __align__(128) float d_h1[NSTREAM][BN];
__device__ __align__(128) float d_h2[NSTREAM][BN];
__device__ __align__(128) float d_xz[2][Bq * Tq * 3 * Eq];
__device__ __align__(128) float d_sem[2][Bq * Eq];
__device__ __align__(128) float d_mid[2][Bq * 2 * Eq];

// ---------------- helpers ----------------
DEV_INLINE float lrelu(float x) { return x > 0.f ? x : 0.2f * x; }
DEV_INLINE float fsigmoid(float x) { return __fdividef(1.f, 1.f + __expf(-x)); }
DEV_INLINE float ftanh(float x) {
    float e = __expf(2.f * x);
    return 1.f - __fdividef(2.f, e + 1.f);
}

// ---------------- K1: pack 0/1 int graphs into bitmasks ----------------
__global__ void k_pack(const int* __restrict__ c1, const int* __restrict__ l1,
                       const int* __restrict__ c2, const int* __restrict__ l2) {
    int idx = blockIdx.x * blockDim.x + threadIdx.x;
    int w = idx & (NWORD - 1);
    int row = idx >> 4;
    int s = row / BN;
    int bn = row - s * BN;
    const int* src = (s == 0) ? c1 : (s == 1) ? l1 : (s == 2) ? c2 : l2;
    src += (size_t)bn * Nq + w * 32;
    unsigned bits = 0u;
#pragma unroll
    for (int j4 = 0; j4 < 8; j4++) {
        int4 v = ((const int4*)src)[j4];
        bits |= (v.x != 0 ? 1u : 0u) << (4 * j4);
        bits |= (v.y != 0 ? 1u : 0u) << (4 * j4 + 1);
        bits |= (v.z != 0 ? 1u : 0u) << (4 * j4 + 2);
        bits |= (v.w != 0 ? 1u : 0u) << (4 * j4 + 3);
    }
    d_gb[s][bn * NWORD + w] = bits;
}

// ======== scalar register-blocked MAC (setup GEMMs) ========
#define MAC_64x128(Xs, Ws, acc, tx, ty)                                          \
    {                                                                            \
        _Pragma("unroll 4") for (int k = 0; k < Eq; k++) {                       \
            float4 wv = *(const float4*)&(Ws)[k * Eq + (tx) * 4];                \
            float xr[8];                                                         \
            _Pragma("unroll") for (int r = 0; r < 8; r++)                        \
                xr[r] = (Xs)[((ty) * 8 + r) * Eq + k];                           \
            _Pragma("unroll") for (int r = 0; r < 8; r++) {                      \
                acc[r][0] = fmaf(xr[r], wv.x, acc[r][0]);                        \
                acc[r][1] = fmaf(xr[r], wv.y, acc[r][1]);                        \
                acc[r][2] = fmaf(xr[r], wv.z, acc[r][2]);                        \
                acc[r][3] = fmaf(xr[r], wv.w, acc[r][3]);                        \
            }                                                                    \
        }                                                                        \
    }

// ---------------- K2: lit = LITERAL @ W_lit ; emb = relu(lit) ----------------
__global__ void k_lit(const float* __restrict__ lit1, const float* __restrict__ lit2,
                      const float* __restrict__ w1, const float* __restrict__ w2) {
    extern __shared__ float sm[];
    float* Ws = sm;
    float* Xs = sm + Eq * Eq;
    int side = blockIdx.x >> 8;
    int tile = blockIdx.x & 255;
    int tid = threadIdx.x;
    const float* W = side ? w2 : w1;
    const float* X = (side ? lit2 : lit1) + (size_t)tile * 64 * Eq;
    {
        float4* w4 = (float4*)Ws; const float4* g4 = (const float4*)W;
        for (int i = tid; i < Eq * Eq / 4; i += 256) w4[i] = g4[i];
        float4* x4 = (float4*)Xs; const float4* h4 = (const float4*)X;
        for (int i = tid; i < 64 * Eq / 4; i += 256) x4[i] = h4[i];
    }
    __syncthreads();
    int tx = tid & 31, ty = tid >> 5;
    float acc[8][4];
#pragma unroll
    for (int r = 0; r < 8; r++)
#pragma unroll
        for (int c = 0; c < 4; c++) acc[r][c] = 0.f;
    MAC_64x128(Xs, Ws, acc, tx, ty);
#pragma unroll
    for (int r = 0; r < 8; r++) {
        int row = tile * 64 + ty * 8 + r;
        float4 v = make_float4(acc[r][0], acc[r][1], acc[r][2], acc[r][3]);
        *(float4*)&d_lit[side][(size_t)row * Eq + tx * 4] = v;
        float4 rv = make_float4(fmaxf(v.x, 0.f), fmaxf(v.y, 0.f), fmaxf(v.z, 0.f), fmaxf(v.w, 0.f));
        *(float4*)&d_emb[side * 2 + 0][(size_t)row * Eq + tx * 4] = rv;
        *(float4*)&d_emb[side * 2 + 1][(size_t)row * Eq + tx * 4] = rv;
    }
}

// ---------------- K3: XZ = SEMANTIC @ gru_k + b_i ----------------
__global__ void k_xz(const float* __restrict__ sem1, const float* __restrict__ sem2,
                     const float* __restrict__ k1, const float* __restrict__ k2,
                     const float* __restrict__ gb1, const float* __restrict__ gb2) {
    extern __shared__ float sm[];
    float* Ws = sm;
    float* Xs = sm + Eq * Eq;
    int side = blockIdx.x >> 5;
    int tile = blockIdx.x & 31;
    int tid = threadIdx.x;
    const float* K = side ? k2 : k1;
    const float* BI = side ? gb2 : gb1;
    const float* X = (side ? sem2 : sem1) + (size_t)tile * 64 * Eq;
    {
        float4* x4 = (float4*)Xs; const float4* h4 = (const float4*)X;
        for (int i = tid; i < 64 * Eq / 4; i += 256) x4[i] = h4[i];
    }
    int tx = tid & 31, ty = tid >> 5;
    for (int ch = 0; ch < 3; ch++) {
        __syncthreads();
        for (int i = tid; i < Eq * Eq; i += 256) {
            int kk = i >> 7; int cc = i & 127;
            Ws[i] = K[kk * 384 + ch * 128 + cc];
        }
        __syncthreads();
        float acc[8][4];
#pragma unroll
        for (int r = 0; r < 8; r++)
#pragma unroll
            for (int c = 0; c < 4; c++) acc[r][c] = 0.f;
        MAC_64x128(Xs, Ws, acc, tx, ty);
        float4 bi = *(const float4*)&BI[ch * 128 + tx * 4];
#pragma unroll
        for (int r = 0; r < 8; r++) {
            int row = tile * 64 + ty * 8 + r;
            float4 v = make_float4(acc[r][0] + bi.x, acc[r][1] + bi.y,
                                   acc[r][2] + bi.z, acc[r][3] + bi.w);
            *(float4*)&d_xz[side][(size_t)row * 384 + ch * 128 + tx * 4] = v;
        }
    }
}

// ---------------- K4: GRU recurrence (register-resident rk) ----------------
__global__ __launch_bounds__(384, 1)
void k_gru(const float* __restrict__ rk1, const float* __restrict__ rk2,
           const float* __restrict__ gb1, const float* __restrict__ gb2) {
    __shared__ float hs[128];
    __shared__ float hzs[384];
    int side = blockIdx.x >> 5;
    int b = blockIdx.x & 31;
    int tid = threadIdx.x;
    const float* rk = side ? rk2 : rk1;
    const float* GB = side ? gb2 : gb1;

    float rkr[128];
#pragma unroll
    for (int d = 0; d < 128; d++) rkr[d] = rk[d * 384 + tid];
    float brv = GB[384 + tid];
    if (tid < 128) hs[tid] = 0.f;
    __syncthreads();

    const float* xzb = d_xz[side] + (size_t)(b * Tq) * 384;
    for (int t = 0; t < Tq; t++) {
        float xz0 = 0.f, xz1 = 0.f, xz2 = 0.f;
        if (tid < 128) {
            const float* xzr = xzb + (size_t)t * 384;
            xz0 = xzr[tid];
            xz1 = xzr[128 + tid];
            xz2 = xzr[256 + tid];
        }
        float a0 = brv, a1 = 0.f, a2 = 0.f, a3 = 0.f;
#pragma unroll
        for (int d = 0; d < 128; d += 4) {
            float4 h4 = *(const float4*)&hs[d];
            a0 = fmaf(h4.x, rkr[d], a0);
            a1 = fmaf(h4.y, rkr[d + 1], a1);
            a2 = fmaf(h4.z, rkr[d + 2], a2);
            a3 = fmaf(h4.w, rkr[d + 3], a3);
        }
        hzs[tid] = (a0 + a1) + (a2 + a3);
        __syncthreads();
        if (tid < 128) {
            float z = fsigmoid(xz0 + hzs[tid]);
            float r = fsigmoid(xz1 + hzs[128 + tid]);
            float hh = ftanh(xz2 + r * hzs[256 + tid]);
            hs[tid] = z * hs[tid] + (1.f - z) * hh;
        }
        __syncthreads();
    }
    if (tid < 128) d_sem[side][b * Eq + tid] = hs[tid];
}

// ---------------- K5: attention scores h1,h2 (iteration 0 only) --------------
__global__ void k_scores(const float* __restrict__ cw1, const float* __restrict__ cb1,
                         const float* __restrict__ cw2, const float* __restrict__ cb2,
                         const float* __restrict__ lw1, const float* __restrict__ lb1,
                         const float* __restrict__ lw2, const float* __restrict__ lb2) {
    __shared__ float w1s[Eq], w2s[Eq];
    int s = blockIdx.x >> 6;
    int bn = (blockIdx.x & 63) * 256 + threadIdx.x;
    const float* w1 = (s & 1) ? lw1 : cw1;
    const float* w2 = (s & 1) ? lw2 : cw2;
    float b1 = ((s & 1) ? lb1 : cb1)[0];
    float b2 = ((s & 1) ? lb2 : cb2)[0];
    if (threadIdx.x < Eq) { w1s[threadIdx.x] = w1[threadIdx.x]; w2s[threadIdx.x] = w2[threadIdx.x]; }
    __syncthreads();
    const float4* er = (const float4*)(d_emb[s] + (size_t)bn * Eq);
    float s1 = 0.f, s2 = 0.f;
#pragma unroll
    for (int k = 0; k < 32; k++) {
        float4 v = er[k];
        s1 += v.x * w1s[4 * k] + v.y * w1s[4 * k + 1] + v.z * w1s[4 * k + 2] + v.w * w1s[4 * k + 3];
        s2 += v.x * w2s[4 * k] + v.y * w2s[4 * k + 1] + v.z * w2s[4 * k + 2] + v.w * w2s[4 * k + 3];
    }
    d_h1[s][bn] = s1 + b1;
    d_h2[s][bn] = s2 + b2;
}

// ---------------- K7: fused attention apply (register A-frag + fused softmax) --
constexpr int EJS = 136;   // embJ stride (B operand: ≡8 mod 32)
__global__ void k_av() {
    extern __shared__ float sm[];
    float* embJ = sm;                          // [64][136]
    float* h2all = sm + 64 * EJS;              // [512]
    unsigned* gbs = (unsigned*)(h2all + 512);  // [128][16]

    int bx = blockIdx.x;
    int s = bx >> 7;
    int rem = bx & 127;
    int b = rem >> 2;
    int it = rem & 3;
    int i0 = it * 128;
    int tid = threadIdx.x;
    int w = tid >> 5, lane = tid & 31;
    int mr = w * 16;
    int g = lane >> 2, tg = lane & 3;
    int row0 = mr + g, row1 = mr + g + 8;

    for (int q = tid; q < 512; q += 256) h2all[q] = d_h2[s][b * Nq + q];
    for (int q = tid; q < 128 * 16; q += 256) {
        int r = q >> 4, wi = q & 15;
        gbs[q] = d_gb[s][(size_t)(b * Nq + i0 + r) * NWORD + wi];
    }
    float h1r0 = d_h1[s][b * Nq + i0 + row0];
    float h1r1 = d_h1[s][b * Nq + i0 + row1];

    float acc[16][4];
#pragma unroll
    for (int r = 0; r < 16; r++)
#pragma unroll
        for (int c = 0; c < 4; c++) acc[r][c] = 0.f;
    float z0 = 0.f, z1 = 0.f;
    __syncthreads();

    for (int jt = 0; jt < 8; jt++) {
        {
            const float* src = d_emb[s] + (size_t)(b * Nq + jt * 64) * Eq;
            for (int q = tid; q < 64 * 32; q += 256) {
                int j = q >> 5, c4 = q & 31;
                *(float4*)&embJ[j * EJS + c4 * 4] = *(const float4*)&src[j * Eq + c4 * 4];
            }
        }
        __syncthreads();
        unsigned m00 = gbs[row0 * 16 + jt * 2], m01 = gbs[row0 * 16 + jt * 2 + 1];
        unsigned m10 = gbs[row1 * 16 + jt * 2], m11 = gbs[row1 * 16 + jt * 2 + 1];
        const float* h2t = h2all + jt * 64;
#pragma unroll
        for (int ks = 0; ks < 8; ks++) {
            int k0 = ks * 8;
            int ja = k0 + tg, jb = ja + 4;
            unsigned mw0 = (ks < 4) ? m00 : m01;
            unsigned mw1 = (ks < 4) ? m10 : m11;
            float ea = h2t[ja], eb = h2t[jb];
            int ba = ja & 31, bb = jb & 31;
            float a0 = ((mw0 >> ba) & 1u) ? __expf(lrelu(h1r0 + ea)) : 0.f;
            float a2 = ((mw0 >> bb) & 1u) ? __expf(lrelu(h1r0 + eb)) : 0.f;
            float a1 = ((mw1 >> ba) & 1u) ? __expf(lrelu(h1r1 + ea)) : 0.f;
            float a3 = ((mw1 >> bb) & 1u) ? __expf(lrelu(h1r1 + eb)) : 0.f;
            z0 += a0 + a2;
            z1 += a1 + a3;
            unsigned ua0 = __float_as_uint(a0), ua1 = __float_as_uint(a1);
            unsigned ua2 = __float_as_uint(a2), ua3 = __float_as_uint(a3);
#pragma unroll
            for (int nt = 0; nt < 16; nt++) {
                int n = nt * 8;
                unsigned b0 = __float_as_uint(embJ[(k0 + tg) * EJS + n + g]);
                unsigned b1 = __float_as_uint(embJ[(k0 + tg + 4) * EJS + n + g]);
                asm("mma.sync.aligned.m16n8k8.row.col.f32.tf32.tf32.f32 "
                    "{%0,%1,%2,%3}, {%4,%5,%6,%7}, {%8,%9}, {%0,%1,%2,%3};"
                    : "+f"(acc[nt][0]), "+f"(acc[nt][1]), "+f"(acc[nt][2]), "+f"(acc[nt][3])
                    : "r"(ua0), "r"(ua1), "r"(ua2), "r"(ua3), "r"(b0), "r"(b1));
            }
        }
        __syncthreads();
    }
    // row-sum Z over the tg quad (butterfly leaves total in all 4 lanes)
    z0 += __shfl_xor_sync(0xffffffffu, z0, 1);
    z0 += __shfl_xor_sync(0xffffffffu, z0, 2);
    z1 += __shfl_xor_sync(0xffffffffu, z1, 1);
    z1 += __shfl_xor_sync(0xffffffffu, z1, 2);
    float sc0 = z0 > 0.f ? __fdividef(1.f, z0) : 0.f;
    float sc1v = z1 > 0.f ? __fdividef(1.f, z1) : 0.f;

#pragma unroll
    for (int nt = 0; nt < 16; nt++) {
        int n = nt * 8;
        size_t r0 = (size_t)(b * Nq + i0 + row0) * Eq + n + 2 * tg;
        size_t r1 = (size_t)(b * Nq + i0 + row1) * Eq + n + 2 * tg;
        *(float2*)&d_new[s][r0] = make_float2(acc[nt][0] * sc0, acc[nt][1] * sc0);
        *(float2*)&d_new[s][r1] = make_float2(acc[nt][2] * sc1v, acc[nt][3] * sc1v);
    }
}

// ---------------- K8: fused MLP + next-iteration scores ----------------
constexpr int XSS = 132;   // Xs stride (A operand)
constexpr int WSS = 136;   // Ws stride (B operand)
__global__ void k_mlp(const float* __restrict__ W1, const float* __restrict__ W2,
                      const float* __restrict__ cw1, const float* __restrict__ cb1,
                      const float* __restrict__ cw2, const float* __restrict__ cb2,
                      const float* __restrict__ lw1, const float* __restrict__ lb1,
                      const float* __restrict__ lw2, const float* __restrict__ lb2) {
    extern __shared__ float sm[];
    float* Xs = sm;                   // [64][132]
    float* Ws = sm + 64 * XSS;        // [128][136]
    float* w1s = Ws + 128 * WSS;      // [128]
    float* w2s = w1s + 128;           // [128]
    float* sc1 = w2s + 128;           // [64][2]
    float* sc2 = sc1 + 128;           // [64][2]
    int tile = blockIdx.x;
    int tid = threadIdx.x;
    int w = tid >> 5, lane = tid & 31;
    int wm = w >> 1, wn = w & 1;
    int mr = wm * 16, cn = wn * 64;
    int g = lane >> 2, tg = lane & 3;

    int s = tile >> 8;               // 256 tiles per stream
    int lfg = s & 1;
    const float* aw1 = lfg ? lw1 : cw1;
    const float* aw2 = lfg ? lw2 : cw2;
    float ab1 = (lfg ? lb1 : cb1)[0];
    float ab2 = (lfg ? lb2 : cb2)[0];

    const float* X = &d_new[0][0] + (size_t)tile * 64 * Eq;
    for (int q = tid; q < 64 * 32; q += 256) {
        int r = q >> 5, c4 = q & 31;
        *(float4*)&Xs[r * XSS + c4 * 4] = *(const float4*)&X[r * Eq + c4 * 4];
    }
    for (int q = tid; q < 128 * 32; q += 256) {
        int k = q >> 5, c4 = q & 31;
        *(float4*)&Ws[k * WSS + c4 * 4] = *(const float4*)&W1[k * Eq + c4 * 4];
    }
    if (tid < 128) { w1s[tid] = aw1[tid]; w2s[tid] = aw2[tid]; }
    __syncthreads();

    float acc[8][4];
#pragma unroll
    for (int r = 0; r < 8; r++)
#pragma unroll
        for (int c = 0; c < 4; c++) acc[r][c] = 0.f;
#pragma unroll
    for (int ks = 0; ks < 16; ks++) {
        int k0 = ks * 8;
        unsigned a0 = __float_as_uint(Xs[(mr + g) * XSS + k0 + tg]);
        unsigned a1 = __float_as_uint(Xs[(mr + g + 8) * XSS + k0 + tg]);
        unsigned a2 = __float_as_uint(Xs[(mr + g) * XSS + k0 + tg + 4]);
        unsigned a3 = __float_as_uint(Xs[(mr + g + 8) * XSS + k0 + tg + 4]);
#pragma unroll
        for (int nt = 0; nt < 8; nt++) {
            int n = cn + nt * 8;
            unsigned b0 = __float_as_uint(Ws[(k0 + tg) * WSS + n + g]);
            unsigned b1 = __float_as_uint(Ws[(k0 + tg + 4) * WSS + n + g]);
            asm("mma.sync.aligned.m16n8k8.row.col.f32.tf32.tf32.f32 "
                "{%0,%1,%2,%3}, {%4,%5,%6,%7}, {%8,%9}, {%0,%1,%2,%3};"
                : "+f"(acc[nt][0]), "+f"(acc[nt][1]), "+f"(acc[nt][2]), "+f"(acc[nt][3])
                : "r"(a0), "r"(a1), "r"(a2), "r"(a3), "r"(b0), "r"(b1));
        }
    }
    __syncthreads();

#pragma unroll
    for (int nt = 0; nt < 8; nt++) {
        int n = cn + nt * 8;
        Xs[(mr + g) * XSS + n + 2 * tg]         = fmaxf(acc[nt][0], 0.f);
        Xs[(mr + g) * XSS + n + 2 * tg + 1]     = fmaxf(acc[nt][1], 0.f);
        Xs[(mr + g + 8) * XSS + n + 2 * tg]     = fmaxf(acc[nt][2], 0.f);
        Xs[(mr + g + 8) * XSS + n + 2 * tg + 1] = fmaxf(acc[nt][3], 0.f);
    }
    for (int q = tid; q < 128 * 32; q += 256) {
        int k = q >> 5, c4 = q & 31;
        *(float4*)&Ws[k * WSS + c4 * 4] = *(const float4*)&W2[k * Eq + c4 * 4];
    }
    __syncthreads();

#pragma unroll
    for (int r = 0; r < 8; r++)
#pragma unroll
        for (int c = 0; c < 4; c++) acc[r][c] = 0.f;
#pragma unroll
    for (int ks = 0; ks < 16; ks++) {
        int k0 = ks * 8;
        unsigned a0 = __float_as_uint(Xs[(mr + g) * XSS + k0 + tg]);
        unsigned a1 = __float_as_uint(Xs[(mr + g + 8) * XSS + k0 + tg]);
        unsigned a2 = __float_as_uint(Xs[(mr + g) * XSS + k0 + tg + 4]);
        unsigned a3 = __float_as_uint(Xs[(mr + g + 8) * XSS + k0 + tg + 4]);
#pragma unroll
        for (int nt = 0; nt < 8; nt++) {
            int n = cn + nt * 8;
            unsigned b0 = __float_as_uint(Ws[(k0 + tg) * WSS + n + g]);
            unsigned b1 = __float_as_uint(Ws[(k0 + tg + 4) * WSS + n + g]);
            asm("mma.sync.aligned.m16n8k8.row.col.f32.tf32.tf32.f32 "
                "{%0,%1,%2,%3}, {%4,%5,%6,%7}, {%8,%9}, {%0,%1,%2,%3};"
                : "+f"(acc[nt][0]), "+f"(acc[nt][1]), "+f"(acc[nt][2]), "+f"(acc[nt][3])
                : "r"(a0), "r"(a1), "r"(a2), "r"(a3), "r"(b0), "r"(b1));
        }
    }

    int side = s >> 1;
    int rbase = tile * 64 - s * BN;
    float p1[2] = {0.f, 0.f}, p2[2] = {0.f, 0.f};
#pragma unroll
    for (int nt = 0; nt < 8; nt++) {
        int n = cn + nt * 8;
#pragma unroll
        for (int hh = 0; hh < 2; hh++) {
            int rloc = mr + g + hh * 8;
            int row = rbase + rloc;
            float2 lv = *(const float2*)&d_lit[side][(size_t)row * Eq + n + 2 * tg];
            float t0 = ftanh(lv.x + acc[nt][2 * hh + 0]);
            float t1 = ftanh(lv.y + acc[nt][2 * hh + 1]);
            size_t o = ((size_t)tile * 64 + rloc) * Eq + n + 2 * tg;
            *(float2*)&(&d_emb[0][0])[o] = make_float2(t0, t1);
            p1[hh] += t0 * w1s[n + 2 * tg] + t1 * w1s[n + 2 * tg + 1];
            p2[hh] += t0 * w2s[n + 2 * tg] + t1 * w2s[n + 2 * tg + 1];
        }
    }
    // reduce over tg quad; all 4 lanes end with (row, wn-half) sums
#pragma unroll
    for (int hh = 0; hh < 2; hh++) {
        p1[hh] += __shfl_xor_sync(0xffffffffu, p1[hh], 1);
        p1[hh] += __shfl_xor_sync(0xffffffffu, p1[hh], 2);
        p2[hh] += __shfl_xor_sync(0xffffffffu, p2[hh], 1);
        p2[hh] += __shfl_xor_sync(0xffffffffu, p2[hh], 2);
        if (tg == 0) {
            int rloc = mr + g + hh * 8;
            sc1[rloc * 2 + wn] = p1[hh];
            sc2[rloc * 2 + wn] = p2[hh];
        }
    }
    __syncthreads();
    if (tid < 64) {
        int bn = rbase + tid;
        d_h1[s][bn] = sc1[tid * 2] + sc1[tid * 2 + 1] + ab1;
        d_h2[s][bn] = sc2[tid * 2] + sc2[tid * 2 + 1] + ab2;
    }
}

// ---------------- K10: mid = sum_N concat(cfg_e, lfg_e) ----------------
__global__ void k_colsum() {
    int side = blockIdx.x >> 5;
    int b = blockIdx.x & 31;
    int e2 = threadIdx.x;
    int st = side * 2 + (e2 >> 7);
    int e = e2 & 127;
    float sum = 0.f;
    const float* base = d_emb[st] + (size_t)b * Nq * Eq + e;
    for (int i = 0; i < Nq; i++) sum += base[(size_t)i * Eq];
    d_mid[side][b * 256 + e2] = sum;
}

// ---------------- K11: output head + cosine ----------------
__global__ void k_final(const float* __restrict__ Wout, const float* __restrict__ bout,
                        float* __restrict__ out) {
    int b = blockIdx.x;
    int o = threadIdx.x;
    float e[2];
#pragma unroll
    for (int side = 0; side < 2; side++) {
        float a = bout[o];
        const float* mid = d_mid[side] + b * 256;
        for (int k = 0; k < 256; k++) a = fmaf(mid[k], Wout[k * Oq + o], a);
        const float* se = d_sem[side] + b * Eq;
        for (int k = 0; k < 128; k++) a = fmaf(se[k], Wout[(256 + k) * Oq + o], a);
        e[side] = a;
    }
    float p = e[0] * e[1], q0 = e[0] * e[0], q1 = e[1] * e[1];
#pragma unroll
    for (int off = 16; off; off >>= 1) {
        p += __shfl_xor_sync(0xffffffffu, p, off);
        q0 += __shfl_xor_sync(0xffffffffu, q0, off);
        q1 += __shfl_xor_sync(0xffffffffu, q1, off);
    }
    __shared__ float sp[2], s0[2], s1[2];
    if ((o & 31) == 0) { int w = o >> 5; sp[w] = p; s0[w] = q0; s1[w] = q1; }
    __syncthreads();
    if (o == 0) {
        float dot = sp[0] + sp[1];
        float n0 = s0[0] + s0[1];
        float n1 = s1[0] + s1[1];
        out[b] = 0.5f * (1.f + dot * rsqrtf(fmaxf(n0, 1e-12f)) * rsqrtf(fmaxf(n1, 1e-12f)));
    }
}

// ---------------- host launcher ----------------
constexpr int GEMM_SMEM = (Eq * Eq + 64 * Eq) * 4;
constexpr int MLP_SMEM = (64 * XSS + 128 * WSS + 128 + 128 + 128 + 128) * 4;  // 105472
constexpr int AV_SMEM = (64 * EJS + 512) * 4 + 128 * 16 * 4;                  // 45056

extern "C" void kernel_launch(void* const* d_in, const int* in_sizes, int n_in,
                              void* d_out, int out_size) {
    const int* CFG1 = (const int*)d_in[0];
    const int* LFG1 = (const int*)d_in[1];
    const float* LIT1 = (const float*)d_in[2];
    const float* SEM1 = (const float*)d_in[3];
    const int* CFG2 = (const int*)d_in[4];
    const int* LFG2 = (const int*)d_in[5];
    const float* LIT2 = (const float*)d_in[6];
    const float* SEM2 = (const float*)d_in[7];
    const float* Wlit1 = (const float*)d_in[8];
    const float* gk1 = (const float*)d_in[9];
    const float* grk1 = (const float*)d_in[10];
    const float* gb1 = (const float*)d_in[11];
    const float* Wlit2 = (const float*)d_in[12];
    const float* gk2 = (const float*)d_in[13];
    const float* grk2 = (const float*)d_in[14];
    const float* gb2 = (const float*)d_in[15];
    const float* ca1w = (const float*)d_in[16];
    const float* ca1b = (const float*)d_in[17];
    const float* ca2w = (const float*)d_in[18];
    const float* ca2b = (const float*)d_in[19];
    const float* la1w = (const float*)d_in[20];
    const float* la1b = (const float*)d_in[21];
    const float* la2w = (const float*)d_in[22];
    const float* la2b = (const float*)d_in[23];
    const float* mlp1 = (const float*)d_in[24];
    const float* mlp2 = (const float*)d_in[25];
    const float* Wout = (const float*)d_in[26];
    const float* bout = (const float*)d_in[27];
    float* out = (float*)d_out;

    cudaFuncSetAttribute(k_lit, cudaFuncAttributeMaxDynamicSharedMemorySize, GEMM_SMEM);
    cudaFuncSetAttribute(k_xz, cudaFuncAttributeMaxDynamicSharedMemorySize, GEMM_SMEM);
    cudaFuncSetAttribute(k_av, cudaFuncAttributeMaxDynamicSharedMemorySize, AV_SMEM);
    cudaFuncSetAttribute(k_mlp, cudaFuncAttributeMaxDynamicSharedMemorySize, MLP_SMEM);

    k_pack<<<4 * BN * NWORD / 256, 256>>>(CFG1, LFG1, CFG2, LFG2);
    k_lit<<<512, 256, GEMM_SMEM>>>(LIT1, LIT2, Wlit1, Wlit2);
    k_xz<<<64, 256, GEMM_SMEM>>>(SEM1, SEM2, gk1, gk2, gb1, gb2);
    k_gru<<<64, 384>>>(grk1, grk2, gb1, gb2);
    k_scores<<<256, 256>>>(ca1w, ca1b, ca2w, ca2b, la1w, la1b, la2w, la2b);

    for (int it = 0; it < N_ITERS; it++) {
        k_av<<<NSTREAM * Bq * 4, 256, AV_SMEM>>>();
        k_mlp<<<1024, 256, MLP_SMEM>>>(mlp1, mlp2,
                                       ca1w, ca1b, ca2w, ca2b,
                                       la1w, la1b, la2w, la2b);
    }
    k_colsum<<<64, 256>>>();
    k_final<<<32, 64>>>(Wout, bout, out);
}